// round 7
// baseline (speedup 1.0000x reference)
#include <cuda_runtime.h>
#include <cuda_fp16.h>
#include <math.h>

#define Bdim 2
#define Ndim 1024
#define Ddim 1024
#define Hdim 16
#define Sdim 4
#define DHdim 64
#define NNdim (Ndim*Ndim)
#define KT 32

// ---------------- static scratch (no allocation allowed) ----------------
__device__ float  g_q[Sdim*Bdim*Ndim*Ddim];           // 32 MB
__device__ float  g_k[Sdim*Bdim*Ndim*Ddim];           // 32 MB
__device__ float  g_v[Sdim*Bdim*Ndim*Ddim];           // 32 MB
__device__ __half g_ph[(size_t)Sdim*Bdim*Hdim*NNdim]; // 256 MB probs (fp16)
__device__ float  g_comb[Bdim*Ndim*Ddim];             // 8 MB combined
__device__ float  g_xmean[Bdim*Ddim];
__device__ float  g_params[16];                       // [0]=1/temp, [1..4]=gw, [5..12]=coh[b][s]

// ---------------- helpers ----------------
__device__ __forceinline__ unsigned f2tf32(float x) {
    unsigned u;
    asm("cvt.rna.tf32.f32 %0, %1;" : "=r"(u) : "f"(x));
    return u;
}

__device__ __forceinline__ void mma_tf32(float* d, const unsigned* a, const unsigned* b) {
    asm volatile(
        "mma.sync.aligned.m16n8k8.row.col.f32.tf32.tf32.f32 "
        "{%0,%1,%2,%3},{%4,%5,%6,%7},{%8,%9},{%0,%1,%2,%3};"
        : "+f"(d[0]), "+f"(d[1]), "+f"(d[2]), "+f"(d[3])
        : "r"(a[0]), "r"(a[1]), "r"(a[2]), "r"(a[3]), "r"(b[0]), "r"(b[1]));
}

// ---------------- mean pool over tokens ----------------
__global__ void xmean_kernel(const float* __restrict__ x) {
    int idx = blockIdx.x * blockDim.x + threadIdx.x;  // b*D + d
    if (idx >= Bdim * Ddim) return;
    int b = idx / Ddim, d = idx % Ddim;
    const float* p = x + (long long)b * Ndim * Ddim + d;
    float acc = 0.f;
    for (int n = 0; n < Ndim; n++) acc += p[(long long)n * Ddim];
    g_xmean[idx] = acc * (1.0f / Ndim);
}

// ---------------- temp clip, gate weights, coherence gate ----------------
__global__ void prep_kernel(const float* __restrict__ Wg, const float* __restrict__ bg,
                            const float* __restrict__ hyp_w,
                            const float* __restrict__ temperature) {
    int t = threadIdx.x;
    int warp = t / 32, lane = t % 32;
    if (warp < Bdim * Sdim) {
        int b = warp / Sdim, s = warp % Sdim;
        float acc = 0.f;
        for (int d = lane; d < Ddim; d += 32)
            acc += g_xmean[b * Ddim + d] * Wg[s * Ddim + d];
        #pragma unroll
        for (int o = 16; o > 0; o >>= 1) acc += __shfl_down_sync(0xffffffff, acc, o);
        if (lane == 0) {
            float vv = acc + bg[s];
            g_params[5 + b * Sdim + s] = 1.0f / (1.0f + expf(-vv));
        }
    }
    if (t == 0) {
        float tp = fminf(fmaxf(temperature[0], 0.1f), 10.0f);
        g_params[0] = 1.0f / tp;
        float hw[Sdim];
        float m = -1e30f;
        for (int s = 0; s < Sdim; s++) { hw[s] = hyp_w[s] / tp; m = fmaxf(m, hw[s]); }
        float sum = 0.f;
        for (int s = 0; s < Sdim; s++) { hw[s] = expf(hw[s] - m); sum += hw[s]; }
        for (int s = 0; s < Sdim; s++) g_params[1 + s] = hw[s] / sum;
    }
}

// ---------------- tensor-core batched C = alpha * A * B^T (+bias), 512 thr ----------------
__global__ void __launch_bounds__(512) gemm_tc512(
    const float* __restrict__ Aall, const float* __restrict__ Ball,
    float* __restrict__ Call, const float* __restrict__ bias,
    int K, int lda, int ldb, int ldc,
    int zmod, long long sAlo, long long sAhi,
    long long sBlo, long long sBhi, long long sClo, long long sChi, float alpha)
{
    constexpr int BM = 128, BN = 128, WM = 32, WN = 32;
    constexpr int MT = WM / 16, NT = WN / 8;   // 2, 4
    constexpr int LDP = 36;
    constexpr int RPP = 512 / 8;               // 64 rows per pass
    constexpr int AI = BM / RPP, BI = BN / RPP; // 2, 2

    extern __shared__ float sm[];
    float* As = sm;                    // [2][BM][LDP]
    float* Bs = sm + 2 * BM * LDP;     // [2][BN][LDP]

    int z = blockIdx.z;
    const float* A  = Aall + (long long)(z % zmod) * sAlo + (long long)(z / zmod) * sAhi;
    const float* Bt = Ball + (long long)(z % zmod) * sBlo + (long long)(z / zmod) * sBhi;
    float* C = Call + (long long)(z % zmod) * sClo + (long long)(z / zmod) * sChi;

    int m0 = blockIdx.y * BM;
    int n0 = blockIdx.x * BN;
    int t = threadIdx.x;
    int lane = t & 31, w = t >> 5;
    int wr = w / (BN / WN), wc = w % (BN / WN);
    int lcol = (t & 7) * 4;
    int lrow = t >> 3;

    float acc[MT][NT][4];
    #pragma unroll
    for (int mt = 0; mt < MT; mt++)
        #pragma unroll
        for (int nt = 0; nt < NT; nt++)
            #pragma unroll
            for (int i = 0; i < 4; i++) acc[mt][nt][i] = 0.f;

    const int numT = K / KT;
    float4 ra[AI], rb[BI];

    auto loadG = [&](int kt) {
        #pragma unroll
        for (int i = 0; i < AI; i++) {
            int r = lrow + i * RPP;
            ra[i] = *(const float4*)(A + (long long)(m0 + r) * lda + kt * KT + lcol);
        }
        #pragma unroll
        for (int i = 0; i < BI; i++) {
            int r = lrow + i * RPP;
            rb[i] = *(const float4*)(Bt + (long long)(n0 + r) * ldb + kt * KT + lcol);
        }
    };
    auto storeS = [&](int buf) {
        #pragma unroll
        for (int i = 0; i < AI; i++) {
            int r = lrow + i * RPP;
            unsigned* d = (unsigned*)(As + buf * BM * LDP + r * LDP + lcol);
            d[0] = f2tf32(ra[i].x); d[1] = f2tf32(ra[i].y);
            d[2] = f2tf32(ra[i].z); d[3] = f2tf32(ra[i].w);
        }
        #pragma unroll
        for (int i = 0; i < BI; i++) {
            int r = lrow + i * RPP;
            unsigned* d = (unsigned*)(Bs + buf * BN * LDP + r * LDP + lcol);
            d[0] = f2tf32(rb[i].x); d[1] = f2tf32(rb[i].y);
            d[2] = f2tf32(rb[i].z); d[3] = f2tf32(rb[i].w);
        }
    };

    loadG(0);
    storeS(0);

    int g = lane >> 2, c4 = lane & 3;
    for (int kt = 0; kt < numT; kt++) {
        __syncthreads();
        int buf = kt & 1;
        if (kt + 1 < numT) loadG(kt + 1);

        const float* Ab = As + buf * BM * LDP;
        const float* Bb = Bs + buf * BN * LDP;
        #pragma unroll
        for (int ks = 0; ks < KT / 8; ks++) {
            int kb = ks * 8 + c4;
            unsigned afr[MT][4], bfr[NT][2];
            #pragma unroll
            for (int mt = 0; mt < MT; mt++) {
                const float* pA = Ab + (wr * WM + mt * 16 + g) * LDP;
                afr[mt][0] = __float_as_uint(pA[kb]);
                afr[mt][1] = __float_as_uint(pA[8 * LDP + kb]);
                afr[mt][2] = __float_as_uint(pA[kb + 4]);
                afr[mt][3] = __float_as_uint(pA[8 * LDP + kb + 4]);
            }
            #pragma unroll
            for (int nt = 0; nt < NT; nt++) {
                const float* pB = Bb + (wc * WN + nt * 8 + g) * LDP;
                bfr[nt][0] = __float_as_uint(pB[kb]);
                bfr[nt][1] = __float_as_uint(pB[kb + 4]);
            }
            #pragma unroll
            for (int mt = 0; mt < MT; mt++)
                #pragma unroll
                for (int nt = 0; nt < NT; nt++)
                    mma_tf32(acc[mt][nt], afr[mt], bfr[nt]);
        }
        if (kt + 1 < numT) storeS(1 - buf);
    }

    #pragma unroll
    for (int mt = 0; mt < MT; mt++) {
        int r = m0 + wr * WM + mt * 16 + g;
        #pragma unroll
        for (int nt = 0; nt < NT; nt++) {
            int c = n0 + wc * WN + nt * 8 + c4 * 2;
            float b0 = 0.f, b1 = 0.f;
            if (bias) { b0 = bias[c]; b1 = bias[c + 1]; }
            float2 v0 = make_float2(acc[mt][nt][0] * alpha + b0,
                                    acc[mt][nt][1] * alpha + b1);
            float2 v1 = make_float2(acc[mt][nt][2] * alpha + b0,
                                    acc[mt][nt][3] * alpha + b1);
            *(float2*)(C + (long long)r * ldc + c) = v0;
            *(float2*)(C + (long long)(r + 8) * ldc + c) = v1;
        }
    }
}

// ---------------- fused QK^T + softmax -> fp16 probs ----------------
// grid: (N/32 m-tiles, S*B*H). block 512 = 16 warps (2 warp-rows x 8 warp-cols).
// Each block: logits tile [32 x 1024] in registers (64 floats/thread),
// K staged in smem chunks of 256 kv-rows, then row softmax + coalesced fp16 store.
#define QS_OFF   0
#define KS_OFF   2176              // 32*68
#define RM_OFF   (KS_OFF + 256*68) // 19584
#define RS_OFF   (RM_OFF + 256)    // 19840
#define PS_OFF   (RS_OFF + 256)    // 20096 (float offset; used as half*)
#define QK_SMEM_FLOATS (PS_OFF + 16512)  // Ps: 32*1032 halves = 16512 floats

__global__ void __launch_bounds__(512) qk_softmax_kernel() {
    extern __shared__ float sm[];
    float* Qs = sm + QS_OFF;            // [32][68]
    float* Ks = sm + KS_OFF;            // [256][68]
    float* redM = sm + RM_OFF;          // [32][8]
    float* redS = sm + RS_OFF;          // [32][8]
    __half* Ps = (__half*)(sm + PS_OFF); // [32][1032]

    int m0 = blockIdx.x * 32;
    int z = blockIdx.y;                 // (s*B + b)*H + h
    int sb = z / Hdim, h = z % Hdim;

    const float* Q = g_q + (size_t)sb * Ndim * Ddim + h * DHdim;
    const float* K = g_k + (size_t)sb * Ndim * Ddim + h * DHdim;
    __half* P = g_ph + (size_t)z * NNdim + (size_t)m0 * Ndim;

    int t = threadIdx.x;
    int lane = t & 31, w = t >> 5;
    int wr = w >> 3, wc = w & 7;        // warp row (0..1), warp col (0..7)
    int g = lane >> 2, c4 = lane & 3;

    // load Q tile [32][64] -> tf32 smem
    {
        int row = t >> 4, colg = (t & 15) * 4;
        float4 qv = *(const float4*)(Q + (size_t)(m0 + row) * Ddim + colg);
        unsigned* d = (unsigned*)(Qs + row * 68 + colg);
        d[0] = f2tf32(qv.x); d[1] = f2tf32(qv.y);
        d[2] = f2tf32(qv.z); d[3] = f2tf32(qv.w);
    }

    float acc[16][4];
    #pragma unroll
    for (int f = 0; f < 16; f++)
        #pragma unroll
        for (int i = 0; i < 4; i++) acc[f][i] = 0.f;

    // 4 chunks of 256 kv rows
    for (int c = 0; c < 4; c++) {
        if (c > 0) __syncthreads();     // previous chunk fully consumed
        {
            int colg = (t & 15) * 4;
            int rbase = t >> 4;         // 0..31
            #pragma unroll
            for (int i = 0; i < 8; i++) {
                int row = rbase + i * 32;
                float4 kv = *(const float4*)(K + (size_t)(c * 256 + row) * Ddim + colg);
                unsigned* d = (unsigned*)(Ks + row * 68 + colg);
                d[0] = f2tf32(kv.x); d[1] = f2tf32(kv.y);
                d[2] = f2tf32(kv.z); d[3] = f2tf32(kv.w);
            }
        }
        __syncthreads();

        #pragma unroll
        for (int ks = 0; ks < 8; ks++) {
            int kb = ks * 8 + c4;
            unsigned afr[4];
            const float* pA = Qs + (wr * 16 + g) * 68;
            afr[0] = __float_as_uint(pA[kb]);
            afr[1] = __float_as_uint(pA[8 * 68 + kb]);
            afr[2] = __float_as_uint(pA[kb + 4]);
            afr[3] = __float_as_uint(pA[8 * 68 + kb + 4]);
            #pragma unroll
            for (int nt = 0; nt < 4; nt++) {
                const float* pB = Ks + (wc * 32 + nt * 8 + g) * 68;
                unsigned bfr[2];
                bfr[0] = __float_as_uint(pB[kb]);
                bfr[1] = __float_as_uint(pB[kb + 4]);
                mma_tf32(acc[c * 4 + nt], afr, bfr);
            }
        }
    }

    // ---- softmax over the 32x1024 tile ----
    float invTS = 0.125f * g_params[0];   // scale * 1/temp
    #pragma unroll
    for (int f = 0; f < 16; f++)
        #pragma unroll
        for (int i = 0; i < 4; i++) acc[f][i] *= invTS;

    int rA = wr * 16 + g, rB = rA + 8;

    // row max
    float mA = -1e30f, mB = -1e30f;
    #pragma unroll
    for (int f = 0; f < 16; f++) {
        mA = fmaxf(mA, fmaxf(acc[f][0], acc[f][1]));
        mB = fmaxf(mB, fmaxf(acc[f][2], acc[f][3]));
    }
    mA = fmaxf(mA, __shfl_xor_sync(0xffffffff, mA, 1));
    mA = fmaxf(mA, __shfl_xor_sync(0xffffffff, mA, 2));
    mB = fmaxf(mB, __shfl_xor_sync(0xffffffff, mB, 1));
    mB = fmaxf(mB, __shfl_xor_sync(0xffffffff, mB, 2));
    if (c4 == 0) { redM[rA * 8 + wc] = mA; redM[rB * 8 + wc] = mB; }
    __syncthreads();
    mA = -1e30f; mB = -1e30f;
    #pragma unroll
    for (int j = 0; j < 8; j++) {
        mA = fmaxf(mA, redM[rA * 8 + j]);
        mB = fmaxf(mB, redM[rB * 8 + j]);
    }

    // exp + row sum
    float sA = 0.f, sB = 0.f;
    #pragma unroll
    for (int f = 0; f < 16; f++) {
        acc[f][0] = __expf(acc[f][0] - mA);
        acc[f][1] = __expf(acc[f][1] - mA);
        acc[f][2] = __expf(acc[f][2] - mB);
        acc[f][3] = __expf(acc[f][3] - mB);
        sA += acc[f][0] + acc[f][1];
        sB += acc[f][2] + acc[f][3];
    }
    sA += __shfl_xor_sync(0xffffffff, sA, 1);
    sA += __shfl_xor_sync(0xffffffff, sA, 2);
    sB += __shfl_xor_sync(0xffffffff, sB, 1);
    sB += __shfl_xor_sync(0xffffffff, sB, 2);
    if (c4 == 0) { redS[rA * 8 + wc] = sA; redS[rB * 8 + wc] = sB; }
    __syncthreads();
    sA = 0.f; sB = 0.f;
    #pragma unroll
    for (int j = 0; j < 8; j++) {
        sA += redS[rA * 8 + j];
        sB += redS[rB * 8 + j];
    }
    float invA = 1.0f / sA, invB = 1.0f / sB;

    // normalized probs -> fp16 staging
    #pragma unroll
    for (int f = 0; f < 16; f++) {
        int col = (f >> 2) * 256 + wc * 32 + (f & 3) * 8 + c4 * 2;
        __half2 ha = __floats2half2_rn(acc[f][0] * invA, acc[f][1] * invA);
        __half2 hb = __floats2half2_rn(acc[f][2] * invB, acc[f][3] * invB);
        *(__half2*)(Ps + rA * 1032 + col) = ha;
        *(__half2*)(Ps + rB * 1032 + col) = hb;
    }
    __syncthreads();

    // coalesced copy to gmem: 32 rows x 1024 halves
    {
        int row = t >> 4, seg = t & 15;
        const uint4* src = (const uint4*)(Ps + row * 1032 + seg * 64);
        uint4* dst = (uint4*)(P + (size_t)row * Ndim + seg * 64);
        #pragma unroll
        for (int i = 0; i < 8; i++) dst[i] = src[i];
    }
}

// ---------------- combined_attn.mean(h): out2[b,i,j] = (1/H) sum_{s,h} gw[s] p ----------------
__global__ void reduce_attn_kernel(float* __restrict__ outAttn) {
    long long idx = (long long)blockIdx.x * blockDim.x + threadIdx.x;  // groups of 4
    if (idx >= (long long)Bdim * NNdim / 4) return;
    int b = (int)(idx / (NNdim / 4));
    long long rem = (idx % (NNdim / 4)) * 4;
    float a0 = 0.f, a1 = 0.f, a2 = 0.f, a3 = 0.f;
    #pragma unroll
    for (int s = 0; s < Sdim; s++) {
        float gwv = g_params[1 + s];
        const __half* base = g_ph + ((long long)(s * Bdim + b) * Hdim) * NNdim + rem;
        float h0 = 0.f, h1 = 0.f, h2 = 0.f, h3 = 0.f;
        #pragma unroll 4
        for (int h = 0; h < Hdim; h++) {
            uint2 u = *(const uint2*)(base + (long long)h * NNdim);
            __half2 p01 = *(__half2*)&u.x, p23 = *(__half2*)&u.y;
            float2 f01 = __half22float2(p01), f23 = __half22float2(p23);
            h0 += f01.x; h1 += f01.y; h2 += f23.x; h3 += f23.y;
        }
        a0 += gwv * h0; a1 += gwv * h1; a2 += gwv * h2; a3 += gwv * h3;
    }
    float4 o = make_float4(a0 * (1.0f / Hdim), a1 * (1.0f / Hdim),
                           a2 * (1.0f / Hdim), a3 * (1.0f / Hdim));
    *(float4*)(outAttn + idx * 4) = o;
}

// ---------------- fused P@V + per-sample gate + hypothesis combine ----------------
__global__ void __launch_bounds__(256) pv_combine_kernel() {
    constexpr int BM = 128, BN = 64, WM = 32, WN = 32;
    constexpr int MT = 2, NT = 4;
    constexpr int LDP = 36, LDB2 = 72;
    constexpr int BSZ = KT * LDB2;

    extern __shared__ float sm[];
    float* As = sm;                   // [2][128][36]
    float* Bs = sm + 2 * BM * LDP;    // [2][32][72]

    int zz = blockIdx.y;
    int b = zz / Hdim, h = zz % Hdim;
    int m0 = blockIdx.x * BM;

    int t = threadIdx.x;
    int lane = t & 31, w = t >> 5;
    int wr = w / (BN / WN), wc = w % (BN / WN);
    int lcol = (t & 7) * 4;
    int lrow = t >> 3;
    int bcol = (t % 16) * 4;
    int browk = t / 16;
    int g = lane >> 2, c4 = lane & 3;

    float acc[MT][NT][4];
    #pragma unroll
    for (int mt = 0; mt < MT; mt++)
        #pragma unroll
        for (int nt = 0; nt < NT; nt++)
            #pragma unroll
            for (int i = 0; i < 4; i++) acc[mt][nt][i] = 0.f;

    for (int s = 0; s < Sdim; s++) {
        const __half* A = g_ph + (size_t)((s * Bdim + b) * Hdim + h) * NNdim;
        const float* V = g_v + (size_t)(s * Bdim + b) * Ndim * Ddim + h * DHdim;
        float ws = g_params[1 + s] * g_params[5 + b * Sdim + s];

        uint2 ua[4];
        float4 rbv[2];
        auto loadG = [&](int kt) {
            #pragma unroll
            for (int i = 0; i < 4; i++) {
                int r = lrow + i * 32;
                ua[i] = *(const uint2*)(A + (size_t)(m0 + r) * Ndim + kt * KT + lcol);
            }
            #pragma unroll
            for (int i = 0; i < 2; i++) {
                int kk = browk + i * 16;
                rbv[i] = *(const float4*)(V + (size_t)(kt * KT + kk) * Ddim + bcol);
            }
        };
        auto storeS = [&](int buf) {
            #pragma unroll
            for (int i = 0; i < 4; i++) {
                int r = lrow + i * 32;
                __half2 p01 = *(__half2*)&ua[i].x, p23 = *(__half2*)&ua[i].y;
                float2 f01 = __half22float2(p01), f23 = __half22float2(p23);
                unsigned* d = (unsigned*)(As + buf * BM * LDP + r * LDP + lcol);
                d[0] = f2tf32(f01.x * ws); d[1] = f2tf32(f01.y * ws);
                d[2] = f2tf32(f23.x * ws); d[3] = f2tf32(f23.y * ws);
            }
            #pragma unroll
            for (int i = 0; i < 2; i++) {
                int kk = browk + i * 16;
                unsigned* d = (unsigned*)(Bs + buf * BSZ + kk * LDB2 + bcol);
                d[0] = f2tf32(rbv[i].x); d[1] = f2tf32(rbv[i].y);
                d[2] = f2tf32(rbv[i].z); d[3] = f2tf32(rbv[i].w);
            }
        };

        const int numT = Ndim / KT;   // 32
        loadG(0);
        if (s > 0) __syncthreads();
        storeS(0);
        for (int kt = 0; kt < numT; kt++) {
            __syncthreads();
            int buf = kt & 1;
            if (kt + 1 < numT) loadG(kt + 1);

            const float* Ab = As + buf * BM * LDP;
            const float* Bb = Bs + buf * BSZ;
            #pragma unroll
            for (int ks = 0; ks < KT / 8; ks++) {
                int kb = ks * 8 + c4;
                unsigned afr[MT][4], bfr[NT][2];
                #pragma unroll
                for (int mt = 0; mt < MT; mt++) {
                    const float* pA = Ab + (wr * WM + mt * 16 + g) * LDP;
                    afr[mt][0] = __float_as_uint(pA[kb]);
                    afr[mt][1] = __float_as_uint(pA[8 * LDP + kb]);
                    afr[mt][2] = __float_as_uint(pA[kb + 4]);
                    afr[mt][3] = __float_as_uint(pA[8 * LDP + kb + 4]);
                }
                #pragma unroll
                for (int nt = 0; nt < NT; nt++) {
                    int n = wc * WN + nt * 8 + g;
                    bfr[nt][0] = __float_as_uint(Bb[kb * LDB2 + n]);
                    bfr[nt][1] = __float_as_uint(Bb[(kb + 4) * LDB2 + n]);
                }
                #pragma unroll
                for (int mt = 0; mt < MT; mt++)
                    #pragma unroll
                    for (int nt = 0; nt < NT; nt++)
                        mma_tf32(acc[mt][nt], afr[mt], bfr[nt]);
            }
            if (kt + 1 < numT) storeS(1 - buf);
        }
    }

    float* C = g_comb + (size_t)b * Ndim * Ddim + h * DHdim;
    #pragma unroll
    for (int mt = 0; mt < MT; mt++) {
        int r = m0 + wr * WM + mt * 16 + g;
        #pragma unroll
        for (int nt = 0; nt < NT; nt++) {
            int c = wc * WN + nt * 8 + c4 * 2;
            *(float2*)(C + (size_t)r * Ddim + c) =
                make_float2(acc[mt][nt][0], acc[mt][nt][1]);
            *(float2*)(C + (size_t)(r + 8) * Ddim + c) =
                make_float2(acc[mt][nt][2], acc[mt][nt][3]);
        }
    }
}

// ---------------- launch ----------------
extern "C" void kernel_launch(void* const* d_in, const int* in_sizes, int n_in,
                              void* d_out, int out_size) {
    const float* x    = (const float*)d_in[0];
    const float* Wq   = (const float*)d_in[1];
    const float* Wk   = (const float*)d_in[2];
    const float* Wv   = (const float*)d_in[3];
    const float* Wg   = (const float*)d_in[4];
    const float* bg   = (const float*)d_in[5];
    const float* Wo   = (const float*)d_in[6];
    const float* bo   = (const float*)d_in[7];
    const float* hw   = (const float*)d_in[8];
    const float* temp = (const float*)d_in[9];
    float* out = (float*)d_out;

    float *q, *k, *v, *comb;
    cudaGetSymbolAddress((void**)&q, g_q);
    cudaGetSymbolAddress((void**)&k, g_k);
    cudaGetSymbolAddress((void**)&v, g_v);
    cudaGetSymbolAddress((void**)&comb, g_comb);

    const long long ND = (long long)Ndim * Ddim;
    const long long DD = (long long)Ddim * Ddim;

    const int smem_sq = 2 * (128 + 128) * 36 * (int)sizeof(float);          // 73728
    const int smem_pv = (2 * 128 * 36 + 2 * KT * 72) * (int)sizeof(float);  // 55296
    const int smem_qk = QK_SMEM_FLOATS * (int)sizeof(float);                // 146432
    cudaFuncSetAttribute(gemm_tc512,
                         cudaFuncAttributeMaxDynamicSharedMemorySize, smem_sq);
    cudaFuncSetAttribute(pv_combine_kernel,
                         cudaFuncAttributeMaxDynamicSharedMemorySize, smem_pv);
    cudaFuncSetAttribute(qk_softmax_kernel,
                         cudaFuncAttributeMaxDynamicSharedMemorySize, smem_qk);

    // 1) mean pool + gates
    xmean_kernel<<<(Bdim * Ddim + 255) / 256, 256>>>(x);
    prep_kernel<<<1, 256>>>(Wg, bg, hw, temp);

    // 2) projections: q/k/v[s,b] = x[b] @ W[s]^T   (z = s*B + b)
    dim3 gproj(Ndim / 128, Ndim / 128, Sdim * Bdim);
    gemm_tc512<<<gproj, 512, smem_sq>>>(
        x, Wq, q, nullptr, Ddim, Ddim, Ddim, Ddim,
        Bdim, ND, 0LL, 0LL, DD, ND, (long long)Bdim * ND, 1.0f);
    gemm_tc512<<<gproj, 512, smem_sq>>>(
        x, Wk, k, nullptr, Ddim, Ddim, Ddim, Ddim,
        Bdim, ND, 0LL, 0LL, DD, ND, (long long)Bdim * ND, 1.0f);
    gemm_tc512<<<gproj, 512, smem_sq>>>(
        x, Wv, v, nullptr, Ddim, Ddim, Ddim, Ddim,
        Bdim, ND, 0LL, 0LL, DD, ND, (long long)Bdim * ND, 1.0f);

    // 3) fused QK^T + softmax -> fp16 probs
    dim3 gqk(Ndim / 32, Sdim * Bdim * Hdim);
    qk_softmax_kernel<<<gqk, 512, smem_qk>>>();

    // 4) combined_attn mean over h -> second output
    reduce_attn_kernel<<<(unsigned)((Bdim * (long long)NNdim / 4 + 255) / 256), 256>>>(
        out + (long long)Bdim * ND);

    // 5) fused P@V + gate + combine -> g_comb
    dim3 gpv(Ndim / 128, Bdim * Hdim);
    pv_combine_kernel<<<gpv, 256, smem_pv>>>();

    // 6) y = combined @ Wo^T + bo -> first output
    dim3 gfin(Ndim / 128, Ndim / 128, Bdim);
    gemm_tc512<<<gfin, 512, smem_sq>>>(
        comb, Wo, out, bo, Ddim, Ddim, Ddim, Ddim,
        1, 0LL, ND, 0LL, 0LL, 0LL, ND, 1.0f);
}

// round 8
// speedup vs baseline: 1.4178x; 1.4178x over previous
#include <cuda_runtime.h>
#include <cuda_fp16.h>
#include <math.h>

#define Bdim 2
#define Ndim 1024
#define Ddim 1024
#define Hdim 16
#define Sdim 4
#define DHdim 64
#define NNdim (Ndim*Ndim)
#define KT 32

// ---------------- static scratch (no allocation allowed) ----------------
__device__ float  g_qh_pad0[16];
__device__ __half g_qh[Sdim*Bdim*Ndim*Ddim];          // 16 MB q (fp16)
__device__ __half g_kh[Sdim*Bdim*Ndim*Ddim];          // 16 MB k (fp16)
__device__ float  g_v[Sdim*Bdim*Ndim*Ddim];           // 32 MB v (fp32)
__device__ float  g_p[(size_t)Sdim*Bdim*Hdim*NNdim];  // 512 MB raw dots (fp32)
__device__ __half g_ph[(size_t)Sdim*Bdim*Hdim*NNdim]; // 256 MB probs (fp16)
__device__ float  g_comb[Bdim*Ndim*Ddim];             // 8 MB combined
__device__ float  g_xmean[Bdim*Ddim];
__device__ float  g_params[16];                       // [0]=1/temp, [1..4]=gw, [5..12]=coh[b][s]

// ---------------- helpers ----------------
__device__ __forceinline__ unsigned f2tf32(float x) {
    unsigned u;
    asm("cvt.rna.tf32.f32 %0, %1;" : "=r"(u) : "f"(x));
    return u;
}

__device__ __forceinline__ void mma_tf32(float* d, const unsigned* a, const unsigned* b) {
    asm volatile(
        "mma.sync.aligned.m16n8k8.row.col.f32.tf32.tf32.f32 "
        "{%0,%1,%2,%3},{%4,%5,%6,%7},{%8,%9},{%0,%1,%2,%3};"
        : "+f"(d[0]), "+f"(d[1]), "+f"(d[2]), "+f"(d[3])
        : "r"(a[0]), "r"(a[1]), "r"(a[2]), "r"(a[3]), "r"(b[0]), "r"(b[1]));
}

__device__ __forceinline__ void mma_f16(float* d, const unsigned* a, const unsigned* b) {
    asm volatile(
        "mma.sync.aligned.m16n8k16.row.col.f32.f16.f16.f32 "
        "{%0,%1,%2,%3},{%4,%5,%6,%7},{%8,%9},{%0,%1,%2,%3};"
        : "+f"(d[0]), "+f"(d[1]), "+f"(d[2]), "+f"(d[3])
        : "r"(a[0]), "r"(a[1]), "r"(a[2]), "r"(a[3]), "r"(b[0]), "r"(b[1]));
}

__device__ __forceinline__ unsigned packh2(float x, float y) {
    __half2 h = __floats2half2_rn(x, y);
    return *(unsigned*)&h;
}

// ---------------- mean pool over tokens ----------------
__global__ void xmean_kernel(const float* __restrict__ x) {
    int idx = blockIdx.x * blockDim.x + threadIdx.x;  // b*D + d
    if (idx >= Bdim * Ddim) return;
    int b = idx / Ddim, d = idx % Ddim;
    const float* p = x + (long long)b * Ndim * Ddim + d;
    float acc = 0.f;
    for (int n = 0; n < Ndim; n++) acc += p[(long long)n * Ddim];
    g_xmean[idx] = acc * (1.0f / Ndim);
}

// ---------------- temp clip, gate weights, coherence gate ----------------
__global__ void prep_kernel(const float* __restrict__ Wg, const float* __restrict__ bg,
                            const float* __restrict__ hyp_w,
                            const float* __restrict__ temperature) {
    int t = threadIdx.x;
    int warp = t / 32, lane = t % 32;
    if (warp < Bdim * Sdim) {
        int b = warp / Sdim, s = warp % Sdim;
        float acc = 0.f;
        for (int d = lane; d < Ddim; d += 32)
            acc += g_xmean[b * Ddim + d] * Wg[s * Ddim + d];
        #pragma unroll
        for (int o = 16; o > 0; o >>= 1) acc += __shfl_down_sync(0xffffffff, acc, o);
        if (lane == 0) {
            float vv = acc + bg[s];
            g_params[5 + b * Sdim + s] = 1.0f / (1.0f + expf(-vv));
        }
    }
    if (t == 0) {
        float tp = fminf(fmaxf(temperature[0], 0.1f), 10.0f);
        g_params[0] = 1.0f / tp;
        float hw[Sdim];
        float m = -1e30f;
        for (int s = 0; s < Sdim; s++) { hw[s] = hyp_w[s] / tp; m = fmaxf(m, hw[s]); }
        float sum = 0.f;
        for (int s = 0; s < Sdim; s++) { hw[s] = expf(hw[s] - m); sum += hw[s]; }
        for (int s = 0; s < Sdim; s++) g_params[1 + s] = hw[s] / sum;
    }
}

// ---------------- fp16 tensor-core batched C = alpha * A * B^T (+bias) ----------------
// INHALF: A,B are __half [*, K] row-major; else float (converted to fp16 in smem).
// OUTHALF: C is __half; else float (with optional bias).
// offsets in ELEMENT counts: offX = (z % zmod)*sXlo + (z / zmod)*sXhi
template<bool INHALF, bool OUTHALF>
__global__ void __launch_bounds__(512) gemm16(
    const void* __restrict__ Aall_, const void* __restrict__ Ball_,
    void* __restrict__ Call_, const float* __restrict__ bias,
    int K, int lda, int ldb, int ldc,
    int zmod, long long sAlo, long long sAhi,
    long long sBlo, long long sBhi, long long sClo, long long sChi, float alpha)
{
    constexpr int BM = 128, BN = 128, WM = 32, WN = 32;
    constexpr int MT = 2, NT = 4;
    constexpr int LDW = 20;   // 32-bit words per smem row (40 halves: 32 data + 8 pad)

    __shared__ unsigned smw[2 * 2 * BM * LDW];   // 40 KB: A then B, double buffered
    unsigned* As = smw;
    unsigned* Bs = smw + 2 * BM * LDW;

    int z = blockIdx.z;
    long long offA = (long long)(z % zmod) * sAlo + (long long)(z / zmod) * sAhi;
    long long offB = (long long)(z % zmod) * sBlo + (long long)(z / zmod) * sBhi;
    long long offC = (long long)(z % zmod) * sClo + (long long)(z / zmod) * sChi;

    int m0 = blockIdx.y * BM;
    int n0 = blockIdx.x * BN;
    int t = threadIdx.x;
    int lane = t & 31, w = t >> 5;
    int wr = w >> 2, wc = w & 3;
    int g = lane >> 2, c4 = lane & 3;

    float acc[MT][NT][4];
    #pragma unroll
    for (int mt = 0; mt < MT; mt++)
        #pragma unroll
        for (int nt = 0; nt < NT; nt++)
            #pragma unroll
            for (int i = 0; i < 4; i++) acc[mt][nt][i] = 0.f;

    const int numT = K / KT;

    // loader state
    float4 raf[2], rbf[2];
    uint4 rah, rbh;

    int lrowF = t >> 3, lcolF = (t & 7) * 4;   // fp32 in: 64 rows/pass, 2 passes
    int lrowH = t >> 2, lcolW = (t & 3) * 4;   // fp16 in: 128 rows/pass, 1 pass

    auto loadG = [&](int kt) {
        if constexpr (INHALF) {
            const __half* A = (const __half*)Aall_ + offA;
            const __half* B = (const __half*)Ball_ + offB;
            rah = *(const uint4*)(A + (long long)(m0 + lrowH) * lda + kt * KT + lcolW * 2);
            rbh = *(const uint4*)(B + (long long)(n0 + lrowH) * ldb + kt * KT + lcolW * 2);
        } else {
            const float* A = (const float*)Aall_ + offA;
            const float* B = (const float*)Ball_ + offB;
            #pragma unroll
            for (int i = 0; i < 2; i++) {
                int r = lrowF + i * 64;
                raf[i] = *(const float4*)(A + (long long)(m0 + r) * lda + kt * KT + lcolF);
                rbf[i] = *(const float4*)(B + (long long)(n0 + r) * ldb + kt * KT + lcolF);
            }
        }
    };
    auto storeS = [&](int buf) {
        if constexpr (INHALF) {
            *(uint4*)(As + buf * BM * LDW + lrowH * LDW + lcolW) = rah;
            *(uint4*)(Bs + buf * BM * LDW + lrowH * LDW + lcolW) = rbh;
        } else {
            #pragma unroll
            for (int i = 0; i < 2; i++) {
                int r = lrowF + i * 64;
                unsigned* da = As + buf * BM * LDW + r * LDW + (t & 7) * 2;
                da[0] = packh2(raf[i].x, raf[i].y);
                da[1] = packh2(raf[i].z, raf[i].w);
                unsigned* db = Bs + buf * BM * LDW + r * LDW + (t & 7) * 2;
                db[0] = packh2(rbf[i].x, rbf[i].y);
                db[1] = packh2(rbf[i].z, rbf[i].w);
            }
        }
    };

    loadG(0);
    storeS(0);

    for (int kt = 0; kt < numT; kt++) {
        __syncthreads();
        int buf = kt & 1;
        if (kt + 1 < numT) loadG(kt + 1);

        const unsigned* Ab = As + buf * BM * LDW;
        const unsigned* Bb = Bs + buf * BM * LDW;
        #pragma unroll
        for (int ks = 0; ks < 2; ks++) {            // two k16 steps per 32-wide tile
            int kb = ks * 8 + c4;
            unsigned afr[MT][4], bfr[NT][2];
            #pragma unroll
            for (int mt = 0; mt < MT; mt++) {
                const unsigned* pA = Ab + (wr * WM + mt * 16 + g) * LDW;
                afr[mt][0] = pA[kb];
                afr[mt][1] = pA[8 * LDW + kb];
                afr[mt][2] = pA[kb + 4];
                afr[mt][3] = pA[8 * LDW + kb + 4];
            }
            #pragma unroll
            for (int nt = 0; nt < NT; nt++) {
                const unsigned* pB = Bb + (wc * WN + nt * 8 + g) * LDW;
                bfr[nt][0] = pB[kb];
                bfr[nt][1] = pB[kb + 4];
            }
            #pragma unroll
            for (int mt = 0; mt < MT; mt++)
                #pragma unroll
                for (int nt = 0; nt < NT; nt++)
                    mma_f16(acc[mt][nt], afr[mt], bfr[nt]);
        }
        if (kt + 1 < numT) storeS(1 - buf);
    }

    // epilogue
    #pragma unroll
    for (int mt = 0; mt < MT; mt++) {
        int r = m0 + wr * WM + mt * 16 + g;
        #pragma unroll
        for (int nt = 0; nt < NT; nt++) {
            int c = n0 + wc * WN + nt * 8 + c4 * 2;
            if constexpr (OUTHALF) {
                __half* C = (__half*)Call_ + offC;
                __half2 v0 = __floats2half2_rn(acc[mt][nt][0] * alpha, acc[mt][nt][1] * alpha);
                __half2 v1 = __floats2half2_rn(acc[mt][nt][2] * alpha, acc[mt][nt][3] * alpha);
                *(__half2*)(C + (long long)r * ldc + c) = v0;
                *(__half2*)(C + (long long)(r + 8) * ldc + c) = v1;
            } else {
                float* C = (float*)Call_ + offC;
                float b0 = 0.f, b1 = 0.f;
                if (bias) { b0 = bias[c]; b1 = bias[c + 1]; }
                *(float2*)(C + (long long)r * ldc + c) =
                    make_float2(acc[mt][nt][0] * alpha + b0, acc[mt][nt][1] * alpha + b1);
                *(float2*)(C + (long long)(r + 8) * ldc + c) =
                    make_float2(acc[mt][nt][2] * alpha + b0, acc[mt][nt][3] * alpha + b1);
            }
        }
    }
}

// ---------------- softmax: fp32 dots -> fp16 probs ----------------
__global__ void softmax_kernel() {
    long long row = blockIdx.x;
    int t = threadIdx.x;
    int lane = t & 31, warp = t >> 5;
    const float4* src = (const float4*)(g_p + row * Ndim);
    float4 v = src[t];
    float invT = g_params[0];
    v.x *= invT; v.y *= invT; v.z *= invT; v.w *= invT;

    __shared__ float red[16];
    float mx = fmaxf(fmaxf(v.x, v.y), fmaxf(v.z, v.w));
    #pragma unroll
    for (int o = 16; o > 0; o >>= 1) mx = fmaxf(mx, __shfl_xor_sync(0xffffffff, mx, o));
    if (lane == 0) red[warp] = mx;
    __syncthreads();
    float m = -1e30f;
    #pragma unroll
    for (int i = 0; i < 8; i++) m = fmaxf(m, red[i]);

    float4 e;
    e.x = __expf(v.x - m); e.y = __expf(v.y - m);
    e.z = __expf(v.z - m); e.w = __expf(v.w - m);
    float sm = e.x + e.y + e.z + e.w;
    #pragma unroll
    for (int o = 16; o > 0; o >>= 1) sm += __shfl_xor_sync(0xffffffff, sm, o);
    if (lane == 0) red[8 + warp] = sm;
    __syncthreads();
    float tot = 0.f;
    #pragma unroll
    for (int i = 0; i < 8; i++) tot += red[8 + i];
    float inv = 1.0f / tot;

    __half2 h01 = __floats2half2_rn(e.x * inv, e.y * inv);
    __half2 h23 = __floats2half2_rn(e.z * inv, e.w * inv);
    uint2 u;
    u.x = *(unsigned*)&h01; u.y = *(unsigned*)&h23;
    ((uint2*)(g_ph + row * Ndim))[t] = u;
}

// ---------------- combined_attn.mean(h): out2[b,i,j] = (1/H) sum_{s,h} gw[s] p ----------------
__global__ void reduce_attn_kernel(float* __restrict__ outAttn) {
    long long idx = (long long)blockIdx.x * blockDim.x + threadIdx.x;  // groups of 4
    if (idx >= (long long)Bdim * NNdim / 4) return;
    int b = (int)(idx / (NNdim / 4));
    long long rem = (idx % (NNdim / 4)) * 4;
    float a0 = 0.f, a1 = 0.f, a2 = 0.f, a3 = 0.f;
    #pragma unroll
    for (int s = 0; s < Sdim; s++) {
        float gwv = g_params[1 + s];
        const __half* base = g_ph + ((long long)(s * Bdim + b) * Hdim) * NNdim + rem;
        float h0 = 0.f, h1 = 0.f, h2 = 0.f, h3 = 0.f;
        #pragma unroll 4
        for (int h = 0; h < Hdim; h++) {
            uint2 u = *(const uint2*)(base + (long long)h * NNdim);
            __half2 p01 = *(__half2*)&u.x, p23 = *(__half2*)&u.y;
            float2 f01 = __half22float2(p01), f23 = __half22float2(p23);
            h0 += f01.x; h1 += f01.y; h2 += f23.x; h3 += f23.y;
        }
        a0 += gwv * h0; a1 += gwv * h1; a2 += gwv * h2; a3 += gwv * h3;
    }
    float4 o = make_float4(a0 * (1.0f / Hdim), a1 * (1.0f / Hdim),
                           a2 * (1.0f / Hdim), a3 * (1.0f / Hdim));
    *(float4*)(outAttn + idx * 4) = o;
}

// ---------------- fused P@V + per-sample gate + hypothesis combine (tf32) ----------------
__global__ void __launch_bounds__(256) pv_combine_kernel() {
    constexpr int BM = 128, BN = 64, WM = 32, WN = 32;
    constexpr int MT = 2, NT = 4;
    constexpr int LDP = 36, LDB2 = 72;
    constexpr int BSZ = KT * LDB2;

    extern __shared__ float sm[];
    float* As = sm;                   // [2][128][36]
    float* Bs = sm + 2 * BM * LDP;    // [2][32][72]

    int zz = blockIdx.y;
    int b = zz / Hdim, h = zz % Hdim;
    int m0 = blockIdx.x * BM;

    int t = threadIdx.x;
    int lane = t & 31, w = t >> 5;
    int wr = w / (BN / WN), wc = w % (BN / WN);
    int lcol = (t & 7) * 4;
    int lrow = t >> 3;
    int bcol = (t % 16) * 4;
    int browk = t / 16;
    int g = lane >> 2, c4 = lane & 3;

    float acc[MT][NT][4];
    #pragma unroll
    for (int mt = 0; mt < MT; mt++)
        #pragma unroll
        for (int nt = 0; nt < NT; nt++)
            #pragma unroll
            for (int i = 0; i < 4; i++) acc[mt][nt][i] = 0.f;

    for (int s = 0; s < Sdim; s++) {
        const __half* A = g_ph + (size_t)((s * Bdim + b) * Hdim + h) * NNdim;
        const float* V = g_v + (size_t)(s * Bdim + b) * Ndim * Ddim + h * DHdim;
        float ws = g_params[1 + s] * g_params[5 + b * Sdim + s];

        uint2 ua[4];
        float4 rbv[2];
        auto loadG = [&](int kt) {
            #pragma unroll
            for (int i = 0; i < 4; i++) {
                int r = lrow + i * 32;
                ua[i] = *(const uint2*)(A + (size_t)(m0 + r) * Ndim + kt * KT + lcol);
            }
            #pragma unroll
            for (int i = 0; i < 2; i++) {
                int kk = browk + i * 16;
                rbv[i] = *(const float4*)(V + (size_t)(kt * KT + kk) * Ddim + bcol);
            }
        };
        auto storeS = [&](int buf) {
            #pragma unroll
            for (int i = 0; i < 4; i++) {
                int r = lrow + i * 32;
                __half2 p01 = *(__half2*)&ua[i].x, p23 = *(__half2*)&ua[i].y;
                float2 f01 = __half22float2(p01), f23 = __half22float2(p23);
                unsigned* d = (unsigned*)(As + buf * BM * LDP + r * LDP + lcol);
                d[0] = f2tf32(f01.x * ws); d[1] = f2tf32(f01.y * ws);
                d[2] = f2tf32(f23.x * ws); d[3] = f2tf32(f23.y * ws);
            }
            #pragma unroll
            for (int i = 0; i < 2; i++) {
                int kk = browk + i * 16;
                unsigned* d = (unsigned*)(Bs + buf * BSZ + kk * LDB2 + bcol);
                d[0] = f2tf32(rbv[i].x); d[1] = f2tf32(rbv[i].y);
                d[2] = f2tf32(rbv[i].z); d[3] = f2tf32(rbv[i].w);
            }
        };

        const int numT = Ndim / KT;   // 32
        loadG(0);
        if (s > 0) __syncthreads();
        storeS(0);
        for (int kt = 0; kt < numT; kt++) {
            __syncthreads();
            int buf = kt & 1;
            if (kt + 1 < numT) loadG(kt + 1);

            const float* Ab = As + buf * BM * LDP;
            const float* Bb = Bs + buf * BSZ;
            #pragma unroll
            for (int ks = 0; ks < KT / 8; ks++) {
                int kb = ks * 8 + c4;
                unsigned afr[MT][4], bfr[NT][2];
                #pragma unroll
                for (int mt = 0; mt < MT; mt++) {
                    const float* pA = Ab + (wr * WM + mt * 16 + g) * LDP;
                    afr[mt][0] = __float_as_uint(pA[kb]);
                    afr[mt][1] = __float_as_uint(pA[8 * LDP + kb]);
                    afr[mt][2] = __float_as_uint(pA[kb + 4]);
                    afr[mt][3] = __float_as_uint(pA[8 * LDP + kb + 4]);
                }
                #pragma unroll
                for (int nt = 0; nt < NT; nt++) {
                    int n = wc * WN + nt * 8 + g;
                    bfr[nt][0] = __float_as_uint(Bb[kb * LDB2 + n]);
                    bfr[nt][1] = __float_as_uint(Bb[(kb + 4) * LDB2 + n]);
                }
                #pragma unroll
                for (int mt = 0; mt < MT; mt++)
                    #pragma unroll
                    for (int nt = 0; nt < NT; nt++)
                        mma_tf32(acc[mt][nt], afr[mt], bfr[nt]);
            }
            if (kt + 1 < numT) storeS(1 - buf);
        }
    }

    float* C = g_comb + (size_t)b * Ndim * Ddim + h * DHdim;
    #pragma unroll
    for (int mt = 0; mt < MT; mt++) {
        int r = m0 + wr * WM + mt * 16 + g;
        #pragma unroll
        for (int nt = 0; nt < NT; nt++) {
            int c = wc * WN + nt * 8 + c4 * 2;
            *(float2*)(C + (size_t)r * Ddim + c) =
                make_float2(acc[mt][nt][0], acc[mt][nt][1]);
            *(float2*)(C + (size_t)(r + 8) * Ddim + c) =
                make_float2(acc[mt][nt][2], acc[mt][nt][3]);
        }
    }
}

// ---------------- launch ----------------
extern "C" void kernel_launch(void* const* d_in, const int* in_sizes, int n_in,
                              void* d_out, int out_size) {
    const float* x    = (const float*)d_in[0];
    const float* Wq   = (const float*)d_in[1];
    const float* Wk   = (const float*)d_in[2];
    const float* Wv   = (const float*)d_in[3];
    const float* Wg   = (const float*)d_in[4];
    const float* bg   = (const float*)d_in[5];
    const float* Wo   = (const float*)d_in[6];
    const float* bo   = (const float*)d_in[7];
    const float* hw   = (const float*)d_in[8];
    const float* temp = (const float*)d_in[9];
    float* out = (float*)d_out;

    void *qh, *kh, *v, *comb, *p;
    cudaGetSymbolAddress(&qh, g_qh);
    cudaGetSymbolAddress(&kh, g_kh);
    cudaGetSymbolAddress(&v, g_v);
    cudaGetSymbolAddress(&comb, g_comb);
    cudaGetSymbolAddress(&p, g_p);

    const long long ND = (long long)Ndim * Ddim;
    const long long DD = (long long)Ddim * Ddim;

    const int smem_pv = (2 * 128 * 36 + 2 * KT * 72) * (int)sizeof(float);  // 55296
    cudaFuncSetAttribute(pv_combine_kernel,
                         cudaFuncAttributeMaxDynamicSharedMemorySize, smem_pv);

    // 1) mean pool + gates
    xmean_kernel<<<(Bdim * Ddim + 255) / 256, 256>>>(x);
    prep_kernel<<<1, 256>>>(Wg, bg, hw, temp);

    // 2) projections: q/k (fp16 out), v (fp32 out)   (z = s*B + b)
    dim3 gproj(Ndim / 128, Ndim / 128, Sdim * Bdim);
    gemm16<false, true><<<gproj, 512>>>(
        x, Wq, qh, nullptr, Ddim, Ddim, Ddim, Ddim,
        Bdim, ND, 0LL, 0LL, DD, ND, (long long)Bdim * ND, 1.0f);
    gemm16<false, true><<<gproj, 512>>>(
        x, Wk, kh, nullptr, Ddim, Ddim, Ddim, Ddim,
        Bdim, ND, 0LL, 0LL, DD, ND, (long long)Bdim * ND, 1.0f);
    gemm16<false, false><<<gproj, 512>>>(
        x, Wv, v, nullptr, Ddim, Ddim, Ddim, Ddim,
        Bdim, ND, 0LL, 0LL, DD, ND, (long long)Bdim * ND, 1.0f);

    // 3) dots[s,b,h] = scale * Q K^T  (fp16 in, fp32 out; z = sb*H + h, zmod=H)
    dim3 gdots(Ndim / 128, Ndim / 128, Sdim * Bdim * Hdim);
    gemm16<true, false><<<gdots, 512>>>(
        qh, kh, p, nullptr, DHdim, Ddim, Ddim, Ndim,
        Hdim, (long long)DHdim, ND, (long long)DHdim, ND,
        (long long)NNdim, (long long)Hdim * NNdim, 0.125f);

    // 4) softmax rows: fp32 dots -> fp16 probs
    softmax_kernel<<<Sdim * Bdim * Hdim * Ndim, 256>>>();

    // 5) combined_attn mean over h -> second output
    reduce_attn_kernel<<<(unsigned)((Bdim * (long long)NNdim / 4 + 255) / 256), 256>>>(
        out + (long long)Bdim * ND);

    // 6) fused P@V + gate + combine -> g_comb
    dim3 gpv(Ndim / 128, Bdim * Hdim);
    pv_combine_kernel<<<gpv, 256, smem_pv>>>();

    // 7) y = combined @ Wo^T + bo -> first output
    dim3 gfin(Ndim / 128, Ndim / 128, Bdim);
    gemm16<false, false><<<gfin, 512>>>(
        comb, Wo, out, bo, Ddim, Ddim, Ddim, Ddim,
        1, 0LL, ND, 0LL, 0LL, 0LL, ND, 1.0f);
}

// round 9
// speedup vs baseline: 1.6515x; 1.1649x over previous
#include <cuda_runtime.h>
#include <cuda_fp16.h>
#include <math.h>

#define Bdim 2
#define Ndim 1024
#define Ddim 1024
#define Hdim 16
#define Sdim 4
#define DHdim 64
#define NNdim (Ndim*Ndim)

// ---------------- static scratch (no allocation allowed) ----------------
__device__ __half g_xh[Bdim*Ndim*Ddim];               // 4 MB x (fp16)
__device__ __half g_wqh[Sdim*Ddim*Ddim];              // 8 MB
__device__ __half g_wkh[Sdim*Ddim*Ddim];              // 8 MB
__device__ __half g_wvh[Sdim*Ddim*Ddim];              // 8 MB
__device__ __half g_woh[Ddim*Ddim];                   // 2 MB
__device__ __half g_qh[Sdim*Bdim*Ndim*Ddim];          // 16 MB q (fp16)
__device__ __half g_kh[Sdim*Bdim*Ndim*Ddim];          // 16 MB k (fp16)
__device__ float  g_v[Sdim*Bdim*Ndim*Ddim];           // 32 MB v (fp32)
__device__ __half g_dh[(size_t)Sdim*Bdim*Hdim*NNdim]; // 256 MB dots (fp16)
__device__ __half g_ph[(size_t)Sdim*Bdim*Hdim*NNdim]; // 256 MB probs (fp16)
__device__ __half g_combh[Bdim*Ndim*Ddim];            // 4 MB combined (fp16)
__device__ float  g_xmean[Bdim*Ddim];
__device__ float  g_params[16];                       // [0]=1/temp, [1..4]=gw, [5..12]=coh[b][s]

// ---------------- helpers ----------------
__device__ __forceinline__ unsigned f2tf32(float x) {
    unsigned u;
    asm("cvt.rna.tf32.f32 %0, %1;" : "=r"(u) : "f"(x));
    return u;
}

__device__ __forceinline__ void mma_tf32(float* d, const unsigned* a, const unsigned* b) {
    asm volatile(
        "mma.sync.aligned.m16n8k8.row.col.f32.tf32.tf32.f32 "
        "{%0,%1,%2,%3},{%4,%5,%6,%7},{%8,%9},{%0,%1,%2,%3};"
        : "+f"(d[0]), "+f"(d[1]), "+f"(d[2]), "+f"(d[3])
        : "r"(a[0]), "r"(a[1]), "r"(a[2]), "r"(a[3]), "r"(b[0]), "r"(b[1]));
}

__device__ __forceinline__ void mma_f16(float* d, const unsigned* a, const unsigned* b) {
    asm volatile(
        "mma.sync.aligned.m16n8k16.row.col.f32.f16.f16.f32 "
        "{%0,%1,%2,%3},{%4,%5,%6,%7},{%8,%9},{%0,%1,%2,%3};"
        : "+f"(d[0]), "+f"(d[1]), "+f"(d[2]), "+f"(d[3])
        : "r"(a[0]), "r"(a[1]), "r"(a[2]), "r"(a[3]), "r"(b[0]), "r"(b[1]));
}

__device__ __forceinline__ void cpa16(unsigned saddr, const void* gptr) {
    asm volatile("cp.async.cg.shared.global [%0], [%1], 16;\n" :: "r"(saddr), "l"(gptr));
}
__device__ __forceinline__ void cpa_commit() {
    asm volatile("cp.async.commit_group;\n");
}

// ---------------- fp32 -> fp16 bulk convert ----------------
__global__ void f2h_kernel(const float* __restrict__ src, __half* __restrict__ dst,
                           long long n) {
    long long i = ((long long)blockIdx.x * blockDim.x + threadIdx.x) * 8;
    if (i >= n) return;
    float4 a = *(const float4*)(src + i);
    float4 b = *(const float4*)(src + i + 4);
    __half2 h0 = __floats2half2_rn(a.x, a.y);
    __half2 h1 = __floats2half2_rn(a.z, a.w);
    __half2 h2 = __floats2half2_rn(b.x, b.y);
    __half2 h3 = __floats2half2_rn(b.z, b.w);
    uint4 u;
    u.x = *(unsigned*)&h0; u.y = *(unsigned*)&h1;
    u.z = *(unsigned*)&h2; u.w = *(unsigned*)&h3;
    *(uint4*)(dst + i) = u;
}

// ---------------- mean pool over tokens ----------------
__global__ void xmean_kernel(const float* __restrict__ x) {
    int idx = blockIdx.x * blockDim.x + threadIdx.x;  // b*D + d
    if (idx >= Bdim * Ddim) return;
    int b = idx / Ddim, d = idx % Ddim;
    const float* p = x + (long long)b * Ndim * Ddim + d;
    float acc = 0.f;
    for (int n = 0; n < Ndim; n++) acc += p[(long long)n * Ddim];
    g_xmean[idx] = acc * (1.0f / Ndim);
}

// ---------------- temp clip, gate weights, coherence gate ----------------
__global__ void prep_kernel(const float* __restrict__ Wg, const float* __restrict__ bg,
                            const float* __restrict__ hyp_w,
                            const float* __restrict__ temperature) {
    int t = threadIdx.x;
    int warp = t / 32, lane = t % 32;
    if (warp < Bdim * Sdim) {
        int b = warp / Sdim, s = warp % Sdim;
        float acc = 0.f;
        for (int d = lane; d < Ddim; d += 32)
            acc += g_xmean[b * Ddim + d] * Wg[s * Ddim + d];
        #pragma unroll
        for (int o = 16; o > 0; o >>= 1) acc += __shfl_down_sync(0xffffffff, acc, o);
        if (lane == 0) {
            float vv = acc + bg[s];
            g_params[5 + b * Sdim + s] = 1.0f / (1.0f + expf(-vv));
        }
    }
    if (t == 0) {
        float tp = fminf(fmaxf(temperature[0], 0.1f), 10.0f);
        g_params[0] = 1.0f / tp;
        float hw[Sdim];
        float m = -1e30f;
        for (int s = 0; s < Sdim; s++) { hw[s] = hyp_w[s] / tp; m = fmaxf(m, hw[s]); }
        float sum = 0.f;
        for (int s = 0; s < Sdim; s++) { hw[s] = expf(hw[s] - m); sum += hw[s]; }
        for (int s = 0; s < Sdim; s++) g_params[1 + s] = hw[s] / sum;
    }
}

// ---------------- all-fp16 tensor-core batched C = alpha * A * B^T (+bias) ----------------
// A: __half [M,K] (lda), B: __half [N,K] (ldb), C row-major (ldc).
// cp.async 3-stage pipeline, KT=64. offsets in elements:
// offX = (z % zmod)*sXlo + (z / zmod)*sXhi
template<bool OUTHALF>
__global__ void __launch_bounds__(512) gemmh(
    const __half* __restrict__ Aall, const __half* __restrict__ Ball,
    void* __restrict__ Call_, const float* __restrict__ bias,
    int K, int lda, int ldb, int ldc,
    int zmod, long long sAlo, long long sAhi,
    long long sBlo, long long sBhi, long long sClo, long long sChi, float alpha)
{
    constexpr int BM = 128, BN = 128, WM = 32, WN = 32;
    constexpr int MT = 2, NT = 4;
    constexpr int KT = 64;
    constexpr int LDW = 36;                   // words per smem row (64 halves + pad)
    constexpr int SLOT = 2 * BM * LDW;        // words per stage (A+B)

    extern __shared__ unsigned smw[];         // 3 stages

    int z = blockIdx.z;
    const __half* A = Aall + (long long)(z % zmod) * sAlo + (long long)(z / zmod) * sAhi;
    const __half* B = Ball + (long long)(z % zmod) * sBlo + (long long)(z / zmod) * sBhi;
    long long offC = (long long)(z % zmod) * sClo + (long long)(z / zmod) * sChi;

    int m0 = blockIdx.y * BM;
    int n0 = blockIdx.x * BN;
    int t = threadIdx.x;
    int lane = t & 31, w = t >> 5;
    int wr = w >> 2, wc = w & 3;
    int g = lane >> 2, c4 = lane & 3;

    unsigned sbase = (unsigned)__cvta_generic_to_shared(smw);

    float acc[MT][NT][4];
    #pragma unroll
    for (int mt = 0; mt < MT; mt++)
        #pragma unroll
        for (int nt = 0; nt < NT; nt++)
            #pragma unroll
            for (int i = 0; i < 4; i++) acc[mt][nt][i] = 0.f;

    const int numT = K / KT;

    // one tile load: A/B each 128 rows x 32 words = 1024 uint4 chunks; 2 per thread.
    auto loadT = [&](int kt, int sl) {
        unsigned sb = sbase + (unsigned)(sl * SLOT) * 4u;
        #pragma unroll
        for (int i = 0; i < 2; i++) {
            int ch = t + i * 512;
            int row = ch >> 3, cw = (ch & 7) * 4;
            cpa16(sb + (unsigned)(row * LDW + cw) * 4u,
                  A + (long long)(m0 + row) * lda + kt * KT + cw * 2);
        }
        #pragma unroll
        for (int i = 0; i < 2; i++) {
            int ch = t + i * 512;
            int row = ch >> 3, cw = (ch & 7) * 4;
            cpa16(sb + (unsigned)(BM * LDW + row * LDW + cw) * 4u,
                  B + (long long)(n0 + row) * ldb + kt * KT + cw * 2);
        }
        cpa_commit();
    };

    loadT(0, 0);
    if (numT > 1) loadT(1, 1);

    for (int kt = 0; kt < numT; kt++) {
        if (kt + 1 < numT) asm volatile("cp.async.wait_group 1;\n");
        else               asm volatile("cp.async.wait_group 0;\n");
        __syncthreads();

        const unsigned* Ab = smw + (kt % 3) * SLOT;
        const unsigned* Bb = Ab + BM * LDW;
        #pragma unroll
        for (int ks = 0; ks < 4; ks++) {
            int kb = ks * 8 + c4;
            unsigned afr[MT][4], bfr[NT][2];
            #pragma unroll
            for (int mt = 0; mt < MT; mt++) {
                const unsigned* pA = Ab + (wr * WM + mt * 16 + g) * LDW;
                afr[mt][0] = pA[kb];
                afr[mt][1] = pA[8 * LDW + kb];
                afr[mt][2] = pA[kb + 4];
                afr[mt][3] = pA[8 * LDW + kb + 4];
            }
            #pragma unroll
            for (int nt = 0; nt < NT; nt++) {
                const unsigned* pB = Bb + (wc * WN + nt * 8 + g) * LDW;
                bfr[nt][0] = pB[kb];
                bfr[nt][1] = pB[kb + 4];
            }
            #pragma unroll
            for (int mt = 0; mt < MT; mt++)
                #pragma unroll
                for (int nt = 0; nt < NT; nt++)
                    mma_f16(acc[mt][nt], afr[mt], bfr[nt]);
        }
        if (kt + 2 < numT) loadT(kt + 2, (kt + 2) % 3);
    }

    // epilogue
    #pragma unroll
    for (int mt = 0; mt < MT; mt++) {
        int r = m0 + wr * WM + mt * 16 + g;
        #pragma unroll
        for (int nt = 0; nt < NT; nt++) {
            int c = n0 + wc * WN + nt * 8 + c4 * 2;
            if constexpr (OUTHALF) {
                __half* C = (__half*)Call_ + offC;
                __half2 v0 = __floats2half2_rn(acc[mt][nt][0] * alpha, acc[mt][nt][1] * alpha);
                __half2 v1 = __floats2half2_rn(acc[mt][nt][2] * alpha, acc[mt][nt][3] * alpha);
                *(__half2*)(C + (long long)r * ldc + c) = v0;
                *(__half2*)(C + (long long)(r + 8) * ldc + c) = v1;
            } else {
                float* C = (float*)Call_ + offC;
                float b0 = 0.f, b1 = 0.f;
                if (bias) { b0 = bias[c]; b1 = bias[c + 1]; }
                *(float2*)(C + (long long)r * ldc + c) =
                    make_float2(acc[mt][nt][0] * alpha + b0, acc[mt][nt][1] * alpha + b1);
                *(float2*)(C + (long long)(r + 8) * ldc + c) =
                    make_float2(acc[mt][nt][2] * alpha + b0, acc[mt][nt][3] * alpha + b1);
            }
        }
    }
}

// ---------------- softmax: fp16 dots -> fp16 probs ----------------
__global__ void softmax_kernel() {
    long long row = blockIdx.x;
    int t = threadIdx.x;
    int lane = t & 31, warp = t >> 5;
    uint2 u = ((const uint2*)(g_dh + row * Ndim))[t];  // 4 halves
    __half2 d01 = *(__half2*)&u.x, d23 = *(__half2*)&u.y;
    float2 f01 = __half22float2(d01), f23 = __half22float2(d23);
    float invT = g_params[0];
    float4 v = make_float4(f01.x * invT, f01.y * invT, f23.x * invT, f23.y * invT);

    __shared__ float red[16];
    float mx = fmaxf(fmaxf(v.x, v.y), fmaxf(v.z, v.w));
    #pragma unroll
    for (int o = 16; o > 0; o >>= 1) mx = fmaxf(mx, __shfl_xor_sync(0xffffffff, mx, o));
    if (lane == 0) red[warp] = mx;
    __syncthreads();
    float m = -1e30f;
    #pragma unroll
    for (int i = 0; i < 8; i++) m = fmaxf(m, red[i]);

    float4 e;
    e.x = __expf(v.x - m); e.y = __expf(v.y - m);
    e.z = __expf(v.z - m); e.w = __expf(v.w - m);
    float sm = e.x + e.y + e.z + e.w;
    #pragma unroll
    for (int o = 16; o > 0; o >>= 1) sm += __shfl_xor_sync(0xffffffff, sm, o);
    if (lane == 0) red[8 + warp] = sm;
    __syncthreads();
    float tot = 0.f;
    #pragma unroll
    for (int i = 0; i < 8; i++) tot += red[8 + i];
    float inv = 1.0f / tot;

    __half2 h01 = __floats2half2_rn(e.x * inv, e.y * inv);
    __half2 h23 = __floats2half2_rn(e.z * inv, e.w * inv);
    uint2 o;
    o.x = *(unsigned*)&h01; o.y = *(unsigned*)&h23;
    ((uint2*)(g_ph + row * Ndim))[t] = o;
}

// ---------------- combined_attn.mean(h): out2[b,i,j] = (1/H) sum_{s,h} gw[s] p ----------------
__global__ void reduce_attn_kernel(float* __restrict__ outAttn) {
    long long idx = (long long)blockIdx.x * blockDim.x + threadIdx.x;  // groups of 4
    if (idx >= (long long)Bdim * NNdim / 4) return;
    int b = (int)(idx / (NNdim / 4));
    long long rem = (idx % (NNdim / 4)) * 4;
    float a0 = 0.f, a1 = 0.f, a2 = 0.f, a3 = 0.f;
    #pragma unroll
    for (int s = 0; s < Sdim; s++) {
        float gwv = g_params[1 + s];
        const __half* base = g_ph + ((long long)(s * Bdim + b) * Hdim) * NNdim + rem;
        float h0 = 0.f, h1 = 0.f, h2 = 0.f, h3 = 0.f;
        #pragma unroll 4
        for (int h = 0; h < Hdim; h++) {
            uint2 u = *(const uint2*)(base + (long long)h * NNdim);
            __half2 p01 = *(__half2*)&u.x, p23 = *(__half2*)&u.y;
            float2 f01 = __half22float2(p01), f23 = __half22float2(p23);
            h0 += f01.x; h1 += f01.y; h2 += f23.x; h3 += f23.y;
        }
        a0 += gwv * h0; a1 += gwv * h1; a2 += gwv * h2; a3 += gwv * h3;
    }
    float4 o = make_float4(a0 * (1.0f / Hdim), a1 * (1.0f / Hdim),
                           a2 * (1.0f / Hdim), a3 * (1.0f / Hdim));
    *(float4*)(outAttn + idx * 4) = o;
}

// ---------------- fused P@V + per-sample gate + hypothesis combine (tf32) ----------------
__global__ void __launch_bounds__(256) pv_combine_kernel() {
    constexpr int KT2 = 32;
    constexpr int BM = 128, BN = 64, WM = 32, WN = 32;
    constexpr int MT = 2, NT = 4;
    constexpr int LDP = 36, LDB2 = 72;
    constexpr int BSZ = KT2 * LDB2;

    extern __shared__ float sm[];
    float* As = sm;                   // [2][128][36]
    float* Bs = sm + 2 * BM * LDP;    // [2][32][72]

    int zz = blockIdx.y;
    int b = zz / Hdim, h = zz % Hdim;
    int m0 = blockIdx.x * BM;

    int t = threadIdx.x;
    int lane = t & 31, w = t >> 5;
    int wr = w / (BN / WN), wc = w % (BN / WN);
    int lcol = (t & 7) * 4;
    int lrow = t >> 3;
    int bcol = (t % 16) * 4;
    int browk = t / 16;
    int g = lane >> 2, c4 = lane & 3;

    float acc[MT][NT][4];
    #pragma unroll
    for (int mt = 0; mt < MT; mt++)
        #pragma unroll
        for (int nt = 0; nt < NT; nt++)
            #pragma unroll
            for (int i = 0; i < 4; i++) acc[mt][nt][i] = 0.f;

    for (int s = 0; s < Sdim; s++) {
        const __half* A = g_ph + (size_t)((s * Bdim + b) * Hdim + h) * NNdim;
        const float* V = g_v + (size_t)(s * Bdim + b) * Ndim * Ddim + h * DHdim;
        float ws = g_params[1 + s] * g_params[5 + b * Sdim + s];

        uint2 ua[4];
        float4 rbv[2];
        auto loadG = [&](int kt) {
            #pragma unroll
            for (int i = 0; i < 4; i++) {
                int r = lrow + i * 32;
                ua[i] = *(const uint2*)(A + (size_t)(m0 + r) * Ndim + kt * KT2 + lcol);
            }
            #pragma unroll
            for (int i = 0; i < 2; i++) {
                int kk = browk + i * 16;
                rbv[i] = *(const float4*)(V + (size_t)(kt * KT2 + kk) * Ddim + bcol);
            }
        };
        auto storeS = [&](int buf) {
            #pragma unroll
            for (int i = 0; i < 4; i++) {
                int r = lrow + i * 32;
                __half2 p01 = *(__half2*)&ua[i].x, p23 = *(__half2*)&ua[i].y;
                float2 f01 = __half22float2(p01), f23 = __half22float2(p23);
                unsigned* d = (unsigned*)(As + buf * BM * LDP + r * LDP + lcol);
                d[0] = f2tf32(f01.x * ws); d[1] = f2tf32(f01.y * ws);
                d[2] = f2tf32(f23.x * ws); d[3] = f2tf32(f23.y * ws);
            }
            #pragma unroll
            for (int i = 0; i < 2; i++) {
                int kk = browk + i * 16;
                unsigned* d = (unsigned*)(Bs + buf * BSZ + kk * LDB2 + bcol);
                d[0] = f2tf32(rbv[i].x); d[1] = f2tf32(rbv[i].y);
                d[2] = f2tf32(rbv[i].z); d[3] = f2tf32(rbv[i].w);
            }
        };

        const int numT = Ndim / KT2;   // 32
        loadG(0);
        if (s > 0) __syncthreads();
        storeS(0);
        for (int kt = 0; kt < numT; kt++) {
            __syncthreads();
            int buf = kt & 1;
            if (kt + 1 < numT) loadG(kt + 1);

            const float* Ab = As + buf * BM * LDP;
            const float* Bb = Bs + buf * BSZ;
            #pragma unroll
            for (int ks = 0; ks < KT2 / 8; ks++) {
                int kb = ks * 8 + c4;
                unsigned afr[MT][4], bfr[NT][2];
                #pragma unroll
                for (int mt = 0; mt < MT; mt++) {
                    const float* pA = Ab + (wr * WM + mt * 16 + g) * LDP;
                    afr[mt][0] = __float_as_uint(pA[kb]);
                    afr[mt][1] = __float_as_uint(pA[8 * LDP + kb]);
                    afr[mt][2] = __float_as_uint(pA[kb + 4]);
                    afr[mt][3] = __float_as_uint(pA[8 * LDP + kb + 4]);
                }
                #pragma unroll
                for (int nt = 0; nt < NT; nt++) {
                    int n = wc * WN + nt * 8 + g;
                    bfr[nt][0] = __float_as_uint(Bb[kb * LDB2 + n]);
                    bfr[nt][1] = __float_as_uint(Bb[(kb + 4) * LDB2 + n]);
                }
                #pragma unroll
                for (int mt = 0; mt < MT; mt++)
                    #pragma unroll
                    for (int nt = 0; nt < NT; nt++)
                        mma_tf32(acc[mt][nt], afr[mt], bfr[nt]);
            }
            if (kt + 1 < numT) storeS(1 - buf);
        }
    }

    __half* C = g_combh + (size_t)b * Ndim * Ddim + h * DHdim;
    #pragma unroll
    for (int mt = 0; mt < MT; mt++) {
        int r = m0 + wr * WM + mt * 16 + g;
        #pragma unroll
        for (int nt = 0; nt < NT; nt++) {
            int c = wc * WN + nt * 8 + c4 * 2;
            *(__half2*)(C + (size_t)r * Ddim + c) =
                __floats2half2_rn(acc[mt][nt][0], acc[mt][nt][1]);
            *(__half2*)(C + (size_t)(r + 8) * Ddim + c) =
                __floats2half2_rn(acc[mt][nt][2], acc[mt][nt][3]);
        }
    }
}

// ---------------- launch ----------------
extern "C" void kernel_launch(void* const* d_in, const int* in_sizes, int n_in,
                              void* d_out, int out_size) {
    const float* x    = (const float*)d_in[0];
    const float* Wq   = (const float*)d_in[1];
    const float* Wk   = (const float*)d_in[2];
    const float* Wv   = (const float*)d_in[3];
    const float* Wg   = (const float*)d_in[4];
    const float* bg   = (const float*)d_in[5];
    const float* Wo   = (const float*)d_in[6];
    const float* bo   = (const float*)d_in[7];
    const float* hw   = (const float*)d_in[8];
    const float* temp = (const float*)d_in[9];
    float* out = (float*)d_out;

    void *xh, *wqh, *wkh, *wvh, *woh, *qh, *kh, *v, *dh, *combh;
    cudaGetSymbolAddress(&xh, g_xh);
    cudaGetSymbolAddress(&wqh, g_wqh);
    cudaGetSymbolAddress(&wkh, g_wkh);
    cudaGetSymbolAddress(&wvh, g_wvh);
    cudaGetSymbolAddress(&woh, g_woh);
    cudaGetSymbolAddress(&qh, g_qh);
    cudaGetSymbolAddress(&kh, g_kh);
    cudaGetSymbolAddress(&v, g_v);
    cudaGetSymbolAddress(&dh, g_dh);
    cudaGetSymbolAddress(&combh, g_combh);

    const long long ND = (long long)Ndim * Ddim;
    const long long DD = (long long)Ddim * Ddim;

    const int smem_g = 3 * 2 * 128 * 36 * 4;                                // 110592
    const int smem_pv = (2 * 128 * 36 + 2 * 32 * 72) * (int)sizeof(float);  // 55296
    cudaFuncSetAttribute(gemmh<true>,
                         cudaFuncAttributeMaxDynamicSharedMemorySize, smem_g);
    cudaFuncSetAttribute(gemmh<false>,
                         cudaFuncAttributeMaxDynamicSharedMemorySize, smem_g);
    cudaFuncSetAttribute(pv_combine_kernel,
                         cudaFuncAttributeMaxDynamicSharedMemorySize, smem_pv);

    // 0) fp16 conversions
    f2h_kernel<<<(unsigned)(Bdim * ND / 8 / 256), 256>>>(x, (__half*)xh, Bdim * ND);
    f2h_kernel<<<(unsigned)(Sdim * DD / 8 / 256), 256>>>(Wq, (__half*)wqh, Sdim * DD);
    f2h_kernel<<<(unsigned)(Sdim * DD / 8 / 256), 256>>>(Wk, (__half*)wkh, Sdim * DD);
    f2h_kernel<<<(unsigned)(Sdim * DD / 8 / 256), 256>>>(Wv, (__half*)wvh, Sdim * DD);
    f2h_kernel<<<(unsigned)(DD / 8 / 256), 256>>>(Wo, (__half*)woh, DD);

    // 1) mean pool + gates
    xmean_kernel<<<(Bdim * Ddim + 255) / 256, 256>>>(x);
    prep_kernel<<<1, 256>>>(Wg, bg, hw, temp);

    // 2) projections: q/k fp16 out, v fp32 out   (z = s*B + b)
    dim3 gproj(Ndim / 128, Ndim / 128, Sdim * Bdim);
    gemmh<true><<<gproj, 512, smem_g>>>(
        (const __half*)xh, (const __half*)wqh, qh, nullptr,
        Ddim, Ddim, Ddim, Ddim,
        Bdim, ND, 0LL, 0LL, DD, ND, (long long)Bdim * ND, 1.0f);
    gemmh<true><<<gproj, 512, smem_g>>>(
        (const __half*)xh, (const __half*)wkh, kh, nullptr,
        Ddim, Ddim, Ddim, Ddim,
        Bdim, ND, 0LL, 0LL, DD, ND, (long long)Bdim * ND, 1.0f);
    gemmh<false><<<gproj, 512, smem_g>>>(
        (const __half*)xh, (const __half*)wvh, v, nullptr,
        Ddim, Ddim, Ddim, Ddim,
        Bdim, ND, 0LL, 0LL, DD, ND, (long long)Bdim * ND, 1.0f);

    // 3) dots[s,b,h] = 0.125 * Q K^T -> fp16   (z = sb*H + h, zmod=H)
    dim3 gdots(Ndim / 128, Ndim / 128, Sdim * Bdim * Hdim);
    gemmh<true><<<gdots, 512, smem_g>>>(
        (const __half*)qh, (const __half*)kh, dh, nullptr,
        DHdim, Ddim, Ddim, Ndim,
        Hdim, (long long)DHdim, ND, (long long)DHdim, ND,
        (long long)NNdim, (long long)Hdim * NNdim, 0.125f);

    // 4) softmax rows: fp16 dots -> fp16 probs
    softmax_kernel<<<Sdim * Bdim * Hdim * Ndim, 256>>>();

    // 5) combined_attn mean over h -> second output
    reduce_attn_kernel<<<(unsigned)((Bdim * (long long)NNdim / 4 + 255) / 256), 256>>>(
        out + (long long)Bdim * ND);

    // 6) fused P@V + gate + combine -> g_combh (fp16)
    dim3 gpv(Ndim / 128, Bdim * Hdim);
    pv_combine_kernel<<<gpv, 256, smem_pv>>>();

    // 7) y = combined @ Wo^T + bo -> first output (fp32 + bias)
    dim3 gfin(Ndim / 128, Ndim / 128, Bdim);
    gemmh<false><<<gfin, 512, smem_g>>>(
        (const __half*)combh, (const __half*)woh, out, bo,
        Ddim, Ddim, Ddim, Ddim,
        1, 0LL, ND, 0LL, 0LL, 0LL, ND, 1.0f);
}

// round 10
// speedup vs baseline: 1.7113x; 1.0362x over previous
#include <cuda_runtime.h>
#include <cuda_fp16.h>
#include <math.h>

#define Bdim 2
#define Ndim 1024
#define Ddim 1024
#define Hdim 16
#define Sdim 4
#define DHdim 64
#define NNdim (Ndim*Ndim)

// ---------------- static scratch (no allocation allowed) ----------------
__device__ __half g_xh[Bdim*Ndim*Ddim];               // 4 MB x (fp16)
__device__ __half g_wqh[Sdim*Ddim*Ddim];              // 8 MB
__device__ __half g_wkh[Sdim*Ddim*Ddim];              // 8 MB
__device__ __half g_wvh[Sdim*Ddim*Ddim];              // 8 MB
__device__ __half g_woh[Ddim*Ddim];                   // 2 MB
__device__ __half g_qh[Sdim*Bdim*Ndim*Ddim];          // 16 MB q (fp16)
__device__ __half g_kh[Sdim*Bdim*Ndim*Ddim];          // 16 MB k (fp16)
__device__ __half g_vh[Sdim*Bdim*Ndim*Ddim];          // 16 MB v (fp16)
__device__ __half g_dh[(size_t)Sdim*Bdim*Hdim*NNdim]; // 256 MB dots (fp16)
__device__ __half g_ph[(size_t)Sdim*Bdim*Hdim*NNdim]; // 256 MB probs (fp16)
__device__ __half g_combh[Bdim*Ndim*Ddim];            // 4 MB combined (fp16)
__device__ float  g_xmean[Bdim*Ddim];
__device__ float  g_params[16];                       // [0]=1/temp, [1..4]=gw, [5..12]=coh[b][s]

// ---------------- helpers ----------------
__device__ __forceinline__ void mma_f16(float* d, const unsigned* a, const unsigned* b) {
    asm volatile(
        "mma.sync.aligned.m16n8k16.row.col.f32.f16.f16.f32 "
        "{%0,%1,%2,%3},{%4,%5,%6,%7},{%8,%9},{%0,%1,%2,%3};"
        : "+f"(d[0]), "+f"(d[1]), "+f"(d[2]), "+f"(d[3])
        : "r"(a[0]), "r"(a[1]), "r"(a[2]), "r"(a[3]), "r"(b[0]), "r"(b[1]));
}

__device__ __forceinline__ void cpa16(unsigned saddr, const void* gptr) {
    asm volatile("cp.async.cg.shared.global [%0], [%1], 16;\n" :: "r"(saddr), "l"(gptr));
}
__device__ __forceinline__ void cpa_commit() {
    asm volatile("cp.async.commit_group;\n");
}

// ---------------- fp32 -> fp16 bulk convert ----------------
__global__ void f2h_kernel(const float* __restrict__ src, __half* __restrict__ dst,
                           long long n) {
    long long i = ((long long)blockIdx.x * blockDim.x + threadIdx.x) * 8;
    if (i >= n) return;
    float4 a = *(const float4*)(src + i);
    float4 b = *(const float4*)(src + i + 4);
    __half2 h0 = __floats2half2_rn(a.x, a.y);
    __half2 h1 = __floats2half2_rn(a.z, a.w);
    __half2 h2 = __floats2half2_rn(b.x, b.y);
    __half2 h3 = __floats2half2_rn(b.z, b.w);
    uint4 u;
    u.x = *(unsigned*)&h0; u.y = *(unsigned*)&h1;
    u.z = *(unsigned*)&h2; u.w = *(unsigned*)&h3;
    *(uint4*)(dst + i) = u;
}

// ---------------- mean pool over tokens ----------------
__global__ void xmean_kernel(const float* __restrict__ x) {
    int idx = blockIdx.x * blockDim.x + threadIdx.x;  // b*D + d
    if (idx >= Bdim * Ddim) return;
    int b = idx / Ddim, d = idx % Ddim;
    const float* p = x + (long long)b * Ndim * Ddim + d;
    float acc = 0.f;
    for (int n = 0; n < Ndim; n++) acc += p[(long long)n * Ddim];
    g_xmean[idx] = acc * (1.0f / Ndim);
}

// ---------------- temp clip, gate weights, coherence gate ----------------
__global__ void prep_kernel(const float* __restrict__ Wg, const float* __restrict__ bg,
                            const float* __restrict__ hyp_w,
                            const float* __restrict__ temperature) {
    int t = threadIdx.x;
    int warp = t / 32, lane = t % 32;
    if (warp < Bdim * Sdim) {
        int b = warp / Sdim, s = warp % Sdim;
        float acc = 0.f;
        for (int d = lane; d < Ddim; d += 32)
            acc += g_xmean[b * Ddim + d] * Wg[s * Ddim + d];
        #pragma unroll
        for (int o = 16; o > 0; o >>= 1) acc += __shfl_down_sync(0xffffffff, acc, o);
        if (lane == 0) {
            float vv = acc + bg[s];
            g_params[5 + b * Sdim + s] = 1.0f / (1.0f + expf(-vv));
        }
    }
    if (t == 0) {
        float tp = fminf(fmaxf(temperature[0], 0.1f), 10.0f);
        g_params[0] = 1.0f / tp;
        float hw[Sdim];
        float m = -1e30f;
        for (int s = 0; s < Sdim; s++) { hw[s] = hyp_w[s] / tp; m = fmaxf(m, hw[s]); }
        float sum = 0.f;
        for (int s = 0; s < Sdim; s++) { hw[s] = expf(hw[s] - m); sum += hw[s]; }
        for (int s = 0; s < Sdim; s++) g_params[1 + s] = hw[s] / sum;
    }
}

// ---------------- all-fp16 tensor-core batched C = alpha * A * B^T (+bias) ----------------
// A: __half [M,K] (lda), B: __half [N,K] (ldb), C row-major (ldc).
// cp.async 3-stage pipeline, KT=64. offsets in elements:
// offX = (z % zmod)*sXlo + (z / zmod)*sXhi
template<bool OUTHALF>
__global__ void __launch_bounds__(512) gemmh(
    const __half* __restrict__ Aall, const __half* __restrict__ Ball,
    void* __restrict__ Call_, const float* __restrict__ bias,
    int K, int lda, int ldb, int ldc,
    int zmod, long long sAlo, long long sAhi,
    long long sBlo, long long sBhi, long long sClo, long long sChi, float alpha)
{
    constexpr int BM = 128, BN = 128, WM = 32, WN = 32;
    constexpr int MT = 2, NT = 4;
    constexpr int KT = 64;
    constexpr int LDW = 36;                   // words per smem row (64 halves + pad)
    constexpr int SLOT = 2 * BM * LDW;        // words per stage (A+B)

    extern __shared__ unsigned smw[];         // 3 stages

    int z = blockIdx.z;
    const __half* A = Aall + (long long)(z % zmod) * sAlo + (long long)(z / zmod) * sAhi;
    const __half* B = Ball + (long long)(z % zmod) * sBlo + (long long)(z / zmod) * sBhi;
    long long offC = (long long)(z % zmod) * sClo + (long long)(z / zmod) * sChi;

    int m0 = blockIdx.y * BM;
    int n0 = blockIdx.x * BN;
    int t = threadIdx.x;
    int lane = t & 31, w = t >> 5;
    int wr = w >> 2, wc = w & 3;
    int g = lane >> 2, c4 = lane & 3;

    unsigned sbase = (unsigned)__cvta_generic_to_shared(smw);

    float acc[MT][NT][4];
    #pragma unroll
    for (int mt = 0; mt < MT; mt++)
        #pragma unroll
        for (int nt = 0; nt < NT; nt++)
            #pragma unroll
            for (int i = 0; i < 4; i++) acc[mt][nt][i] = 0.f;

    const int numT = K / KT;

    auto loadT = [&](int kt, int sl) {
        unsigned sb = sbase + (unsigned)(sl * SLOT) * 4u;
        #pragma unroll
        for (int i = 0; i < 2; i++) {
            int ch = t + i * 512;
            int row = ch >> 3, cw = (ch & 7) * 4;
            cpa16(sb + (unsigned)(row * LDW + cw) * 4u,
                  A + (long long)(m0 + row) * lda + kt * KT + cw * 2);
        }
        #pragma unroll
        for (int i = 0; i < 2; i++) {
            int ch = t + i * 512;
            int row = ch >> 3, cw = (ch & 7) * 4;
            cpa16(sb + (unsigned)(BM * LDW + row * LDW + cw) * 4u,
                  B + (long long)(n0 + row) * ldb + kt * KT + cw * 2);
        }
        cpa_commit();
    };

    loadT(0, 0);
    if (numT > 1) loadT(1, 1);

    for (int kt = 0; kt < numT; kt++) {
        if (kt + 1 < numT) asm volatile("cp.async.wait_group 1;\n");
        else               asm volatile("cp.async.wait_group 0;\n");
        __syncthreads();

        const unsigned* Ab = smw + (kt % 3) * SLOT;
        const unsigned* Bb = Ab + BM * LDW;
        #pragma unroll
        for (int ks = 0; ks < 4; ks++) {
            int kb = ks * 8 + c4;
            unsigned afr[MT][4], bfr[NT][2];
            #pragma unroll
            for (int mt = 0; mt < MT; mt++) {
                const unsigned* pA = Ab + (wr * WM + mt * 16 + g) * LDW;
                afr[mt][0] = pA[kb];
                afr[mt][1] = pA[8 * LDW + kb];
                afr[mt][2] = pA[kb + 4];
                afr[mt][3] = pA[8 * LDW + kb + 4];
            }
            #pragma unroll
            for (int nt = 0; nt < NT; nt++) {
                const unsigned* pB = Bb + (wc * WN + nt * 8 + g) * LDW;
                bfr[nt][0] = pB[kb];
                bfr[nt][1] = pB[kb + 4];
            }
            #pragma unroll
            for (int mt = 0; mt < MT; mt++)
                #pragma unroll
                for (int nt = 0; nt < NT; nt++)
                    mma_f16(acc[mt][nt], afr[mt], bfr[nt]);
        }
        if (kt + 2 < numT) loadT(kt + 2, (kt + 2) % 3);
    }

    // epilogue
    #pragma unroll
    for (int mt = 0; mt < MT; mt++) {
        int r = m0 + wr * WM + mt * 16 + g;
        #pragma unroll
        for (int nt = 0; nt < NT; nt++) {
            int c = n0 + wc * WN + nt * 8 + c4 * 2;
            if constexpr (OUTHALF) {
                __half* C = (__half*)Call_ + offC;
                __half2 v0 = __floats2half2_rn(acc[mt][nt][0] * alpha, acc[mt][nt][1] * alpha);
                __half2 v1 = __floats2half2_rn(acc[mt][nt][2] * alpha, acc[mt][nt][3] * alpha);
                *(__half2*)(C + (long long)r * ldc + c) = v0;
                *(__half2*)(C + (long long)(r + 8) * ldc + c) = v1;
            } else {
                float* C = (float*)Call_ + offC;
                float b0 = 0.f, b1 = 0.f;
                if (bias) { b0 = bias[c]; b1 = bias[c + 1]; }
                *(float2*)(C + (long long)r * ldc + c) =
                    make_float2(acc[mt][nt][0] * alpha + b0, acc[mt][nt][1] * alpha + b1);
                *(float2*)(C + (long long)(r + 8) * ldc + c) =
                    make_float2(acc[mt][nt][2] * alpha + b0, acc[mt][nt][3] * alpha + b1);
            }
        }
    }
}

// ---------------- softmax: fp16 dots -> fp16 probs ----------------
__global__ void softmax_kernel() {
    long long row = blockIdx.x;
    int t = threadIdx.x;
    int lane = t & 31, warp = t >> 5;
    uint2 u = ((const uint2*)(g_dh + row * Ndim))[t];  // 4 halves
    __half2 d01 = *(__half2*)&u.x, d23 = *(__half2*)&u.y;
    float2 f01 = __half22float2(d01), f23 = __half22float2(d23);
    float invT = g_params[0];
    float4 v = make_float4(f01.x * invT, f01.y * invT, f23.x * invT, f23.y * invT);

    __shared__ float red[16];
    float mx = fmaxf(fmaxf(v.x, v.y), fmaxf(v.z, v.w));
    #pragma unroll
    for (int o = 16; o > 0; o >>= 1) mx = fmaxf(mx, __shfl_xor_sync(0xffffffff, mx, o));
    if (lane == 0) red[warp] = mx;
    __syncthreads();
    float m = -1e30f;
    #pragma unroll
    for (int i = 0; i < 8; i++) m = fmaxf(m, red[i]);

    float4 e;
    e.x = __expf(v.x - m); e.y = __expf(v.y - m);
    e.z = __expf(v.z - m); e.w = __expf(v.w - m);
    float sm = e.x + e.y + e.z + e.w;
    #pragma unroll
    for (int o = 16; o > 0; o >>= 1) sm += __shfl_xor_sync(0xffffffff, sm, o);
    if (lane == 0) red[8 + warp] = sm;
    __syncthreads();
    float tot = 0.f;
    #pragma unroll
    for (int i = 0; i < 8; i++) tot += red[8 + i];
    float inv = 1.0f / tot;

    __half2 h01 = __floats2half2_rn(e.x * inv, e.y * inv);
    __half2 h23 = __floats2half2_rn(e.z * inv, e.w * inv);
    uint2 o;
    o.x = *(unsigned*)&h01; o.y = *(unsigned*)&h23;
    ((uint2*)(g_ph + row * Ndim))[t] = o;
}

// ---------------- combined_attn.mean(h): out2[b,i,j] = (1/H) sum_{s,h} gw[s] p ----------------
__global__ void reduce_attn_kernel(float* __restrict__ outAttn) {
    long long idx = (long long)blockIdx.x * blockDim.x + threadIdx.x;  // groups of 4
    if (idx >= (long long)Bdim * NNdim / 4) return;
    int b = (int)(idx / (NNdim / 4));
    long long rem = (idx % (NNdim / 4)) * 4;
    float a0 = 0.f, a1 = 0.f, a2 = 0.f, a3 = 0.f;
    #pragma unroll
    for (int s = 0; s < Sdim; s++) {
        float gwv = g_params[1 + s];
        const __half* base = g_ph + ((long long)(s * Bdim + b) * Hdim) * NNdim + rem;
        float h0 = 0.f, h1 = 0.f, h2 = 0.f, h3 = 0.f;
        #pragma unroll 4
        for (int h = 0; h < Hdim; h++) {
            uint2 u = *(const uint2*)(base + (long long)h * NNdim);
            __half2 p01 = *(__half2*)&u.x, p23 = *(__half2*)&u.y;
            float2 f01 = __half22float2(p01), f23 = __half22float2(p23);
            h0 += f01.x; h1 += f01.y; h2 += f23.x; h3 += f23.y;
        }
        a0 += gwv * h0; a1 += gwv * h1; a2 += gwv * h2; a3 += gwv * h3;
    }
    float4 o = make_float4(a0 * (1.0f / Hdim), a1 * (1.0f / Hdim),
                           a2 * (1.0f / Hdim), a3 * (1.0f / Hdim));
    *(float4*)(outAttn + idx * 4) = o;
}

// ---------------- fused P@V + gate + combine (all fp16 mma) ----------------
// acc[b,i,h*64+dh] = sum_s P_s[i,:] @ (ws * V_s[:,dh])
// A: probs fp16 [128 x 32] per tile (raw). B: V fp16 packed k-pairwise:
// word (k/2)*LDB + n holds halves (k, k+1) for column n, scaled by ws.
__global__ void __launch_bounds__(256) pv_combine_kernel() {
    constexpr int KT2 = 32;
    constexpr int BM = 128, BN = 64, WM = 32, WN = 32;
    constexpr int MT = 2, NT = 4;
    constexpr int LDA = 20;            // words per A row (16 data + 4 pad)
    constexpr int LDB = 72;            // words per B kpair row (64 data + 8 pad)
    constexpr int ASZ = BM * LDA;      // 2560 words
    constexpr int BSZ = (KT2 / 2) * LDB; // 1152 words

    __shared__ unsigned smw[2 * ASZ + 2 * BSZ];   // ~29.7 KB
    unsigned* Aw = smw;
    unsigned* Bw = smw + 2 * ASZ;

    int zz = blockIdx.y;
    int b = zz / Hdim, h = zz % Hdim;
    int m0 = blockIdx.x * BM;

    int t = threadIdx.x;
    int lane = t & 31, w = t >> 5;
    int wr = w >> 1, wc = w & 1;       // 4 warp-rows x 2 warp-cols
    int g = lane >> 2, c4 = lane & 3;
    int kp = t >> 4, ng = t & 15;      // V loader: kpair 0..15, col-group 0..15

    float acc[MT][NT][4];
    #pragma unroll
    for (int mt = 0; mt < MT; mt++)
        #pragma unroll
        for (int nt = 0; nt < NT; nt++)
            #pragma unroll
            for (int i = 0; i < 4; i++) acc[mt][nt][i] = 0.f;

    for (int s = 0; s < Sdim; s++) {
        const __half* A = g_ph + (size_t)((s * Bdim + b) * Hdim + h) * NNdim;
        const __half* V = g_vh + (size_t)(s * Bdim + b) * Ndim * Ddim + h * DHdim;
        float ws = g_params[1 + s] * g_params[5 + b * Sdim + s];
        __half2 ws2 = __float2half2_rn(ws);

        uint4 ua[2];
        uint2 va, vb;
        auto loadG = [&](int kt) {
            #pragma unroll
            for (int i = 0; i < 2; i++) {
                int ch = t + i * 256;
                int row = ch >> 2, cw = (ch & 3) * 4;
                ua[i] = *(const uint4*)(A + (size_t)(m0 + row) * Ndim + kt * KT2 + cw * 2);
            }
            int k = kt * KT2 + kp * 2;
            va = *(const uint2*)(V + (size_t)k * Ddim + ng * 4);
            vb = *(const uint2*)(V + (size_t)(k + 1) * Ddim + ng * 4);
        };
        auto storeS = [&](int buf) {
            #pragma unroll
            for (int i = 0; i < 2; i++) {
                int ch = t + i * 256;
                int row = ch >> 2, cw = (ch & 3) * 4;
                *(uint4*)(Aw + buf * ASZ + row * LDA + cw) = ua[i];
            }
            // interleave (k, k+1) pairs per column, scale by ws
            __half2 a01 = *(__half2*)&va.x, a23 = *(__half2*)&va.y;
            __half2 b01 = *(__half2*)&vb.x, b23 = *(__half2*)&vb.y;
            __half2 w0 = __hmul2(__halves2half2(__low2half(a01), __low2half(b01)), ws2);
            __half2 w1 = __hmul2(__halves2half2(__high2half(a01), __high2half(b01)), ws2);
            __half2 w2 = __hmul2(__halves2half2(__low2half(a23), __low2half(b23)), ws2);
            __half2 w3 = __hmul2(__halves2half2(__high2half(a23), __high2half(b23)), ws2);
            uint4 u;
            u.x = *(unsigned*)&w0; u.y = *(unsigned*)&w1;
            u.z = *(unsigned*)&w2; u.w = *(unsigned*)&w3;
            *(uint4*)(Bw + buf * BSZ + kp * LDB + ng * 4) = u;
        };

        const int numT = Ndim / KT2;   // 32
        loadG(0);
        if (s > 0) __syncthreads();
        storeS(0);
        for (int kt = 0; kt < numT; kt++) {
            __syncthreads();
            int buf = kt & 1;
            if (kt + 1 < numT) loadG(kt + 1);

            const unsigned* Ab = Aw + buf * ASZ;
            const unsigned* Bb = Bw + buf * BSZ;
            #pragma unroll
            for (int ks = 0; ks < 2; ks++) {
                unsigned afr[MT][4], bfr[NT][2];
                #pragma unroll
                for (int mt = 0; mt < MT; mt++) {
                    const unsigned* pA = Ab + (wr * WM + mt * 16 + g) * LDA + ks * 8;
                    afr[mt][0] = pA[c4];
                    afr[mt][1] = pA[8 * LDA + c4];
                    afr[mt][2] = pA[c4 + 4];
                    afr[mt][3] = pA[8 * LDA + c4 + 4];
                }
                #pragma unroll
                for (int nt = 0; nt < NT; nt++) {
                    int n = wc * WN + nt * 8 + g;
                    bfr[nt][0] = Bb[(ks * 8 + c4) * LDB + n];
                    bfr[nt][1] = Bb[(ks * 8 + 4 + c4) * LDB + n];
                }
                #pragma unroll
                for (int mt = 0; mt < MT; mt++)
                    #pragma unroll
                    for (int nt = 0; nt < NT; nt++)
                        mma_f16(acc[mt][nt], afr[mt], bfr[nt]);
            }
            if (kt + 1 < numT) storeS(1 - buf);
        }
    }

    __half* C = g_combh + (size_t)b * Ndim * Ddim + h * DHdim;
    #pragma unroll
    for (int mt = 0; mt < MT; mt++) {
        int r = m0 + wr * WM + mt * 16 + g;
        #pragma unroll
        for (int nt = 0; nt < NT; nt++) {
            int c = wc * WN + nt * 8 + c4 * 2;
            *(__half2*)(C + (size_t)r * Ddim + c) =
                __floats2half2_rn(acc[mt][nt][0], acc[mt][nt][1]);
            *(__half2*)(C + (size_t)(r + 8) * Ddim + c) =
                __floats2half2_rn(acc[mt][nt][2], acc[mt][nt][3]);
        }
    }
}

// ---------------- launch ----------------
extern "C" void kernel_launch(void* const* d_in, const int* in_sizes, int n_in,
                              void* d_out, int out_size) {
    const float* x    = (const float*)d_in[0];
    const float* Wq   = (const float*)d_in[1];
    const float* Wk   = (const float*)d_in[2];
    const float* Wv   = (const float*)d_in[3];
    const float* Wg   = (const float*)d_in[4];
    const float* bg   = (const float*)d_in[5];
    const float* Wo   = (const float*)d_in[6];
    const float* bo   = (const float*)d_in[7];
    const float* hw   = (const float*)d_in[8];
    const float* temp = (const float*)d_in[9];
    float* out = (float*)d_out;

    void *xh, *wqh, *wkh, *wvh, *woh, *qh, *kh, *vh, *dh, *combh;
    cudaGetSymbolAddress(&xh, g_xh);
    cudaGetSymbolAddress(&wqh, g_wqh);
    cudaGetSymbolAddress(&wkh, g_wkh);
    cudaGetSymbolAddress(&wvh, g_wvh);
    cudaGetSymbolAddress(&woh, g_woh);
    cudaGetSymbolAddress(&qh, g_qh);
    cudaGetSymbolAddress(&kh, g_kh);
    cudaGetSymbolAddress(&vh, g_vh);
    cudaGetSymbolAddress(&dh, g_dh);
    cudaGetSymbolAddress(&combh, g_combh);

    const long long ND = (long long)Ndim * Ddim;
    const long long DD = (long long)Ddim * Ddim;

    const int smem_g = 3 * 2 * 128 * 36 * 4;   // 110592
    cudaFuncSetAttribute(gemmh<true>,
                         cudaFuncAttributeMaxDynamicSharedMemorySize, smem_g);
    cudaFuncSetAttribute(gemmh<false>,
                         cudaFuncAttributeMaxDynamicSharedMemorySize, smem_g);

    // 0) fp16 conversions
    f2h_kernel<<<(unsigned)(Bdim * ND / 8 / 256), 256>>>(x, (__half*)xh, Bdim * ND);
    f2h_kernel<<<(unsigned)(Sdim * DD / 8 / 256), 256>>>(Wq, (__half*)wqh, Sdim * DD);
    f2h_kernel<<<(unsigned)(Sdim * DD / 8 / 256), 256>>>(Wk, (__half*)wkh, Sdim * DD);
    f2h_kernel<<<(unsigned)(Sdim * DD / 8 / 256), 256>>>(Wv, (__half*)wvh, Sdim * DD);
    f2h_kernel<<<(unsigned)(DD / 8 / 256), 256>>>(Wo, (__half*)woh, DD);

    // 1) mean pool + gates
    xmean_kernel<<<(Bdim * Ddim + 255) / 256, 256>>>(x);
    prep_kernel<<<1, 256>>>(Wg, bg, hw, temp);

    // 2) projections: q/k/v all fp16 out   (z = s*B + b)
    dim3 gproj(Ndim / 128, Ndim / 128, Sdim * Bdim);
    gemmh<true><<<gproj, 512, smem_g>>>(
        (const __half*)xh, (const __half*)wqh, qh, nullptr,
        Ddim, Ddim, Ddim, Ddim,
        Bdim, ND, 0LL, 0LL, DD, ND, (long long)Bdim * ND, 1.0f);
    gemmh<true><<<gproj, 512, smem_g>>>(
        (const __half*)xh, (const __half*)wkh, kh, nullptr,
        Ddim, Ddim, Ddim, Ddim,
        Bdim, ND, 0LL, 0LL, DD, ND, (long long)Bdim * ND, 1.0f);
    gemmh<true><<<gproj, 512, smem_g>>>(
        (const __half*)xh, (const __half*)wvh, vh, nullptr,
        Ddim, Ddim, Ddim, Ddim,
        Bdim, ND, 0LL, 0LL, DD, ND, (long long)Bdim * ND, 1.0f);

    // 3) dots[s,b,h] = 0.125 * Q K^T -> fp16   (z = sb*H + h, zmod=H)
    dim3 gdots(Ndim / 128, Ndim / 128, Sdim * Bdim * Hdim);
    gemmh<true><<<gdots, 512, smem_g>>>(
        (const __half*)qh, (const __half*)kh, dh, nullptr,
        DHdim, Ddim, Ddim, Ndim,
        Hdim, (long long)DHdim, ND, (long long)DHdim, ND,
        (long long)NNdim, (long long)Hdim * NNdim, 0.125f);

    // 4) softmax rows: fp16 dots -> fp16 probs
    softmax_kernel<<<Sdim * Bdim * Hdim * Ndim, 256>>>();

    // 5) combined_attn mean over h -> second output
    reduce_attn_kernel<<<(unsigned)((Bdim * (long long)NNdim / 4 + 255) / 256), 256>>>(
        out + (long long)Bdim * ND);

    // 6) fused P@V + gate + combine -> g_combh (fp16, fp16 mma)
    dim3 gpv(Ndim / 128, Bdim * Hdim);
    pv_combine_kernel<<<gpv, 256>>>();

    // 7) y = combined @ Wo^T + bo -> first output (fp32 + bias)
    dim3 gfin(Ndim / 128, Ndim / 128, Bdim);
    gemmh<false><<<gfin, 512, smem_g>>>(
        (const __half*)combh, (const __half*)woh, out, bo,
        Ddim, Ddim, Ddim, Ddim,
        1, 0LL, ND, 0LL, 0LL, 0LL, ND, 1.0f);
}

// round 11
// speedup vs baseline: 1.9356x; 1.1311x over previous
#include <cuda_runtime.h>
#include <cuda_fp16.h>
#include <math.h>

#define Bdim 2
#define Ndim 1024
#define Ddim 1024
#define Hdim 16
#define Sdim 4
#define DHdim 64
#define NNdim (Ndim*Ndim)

// ---------------- static scratch (no allocation allowed) ----------------
__device__ __half g_xh[Bdim*Ndim*Ddim];               // 4 MB x (fp16)
__device__ __half g_wqh[Sdim*Ddim*Ddim];              // 8 MB
__device__ __half g_wkh[Sdim*Ddim*Ddim];              // 8 MB
__device__ __half g_wvh[Sdim*Ddim*Ddim];              // 8 MB
__device__ __half g_woh[Ddim*Ddim];                   // 2 MB
__device__ __half g_qh[Sdim*Bdim*Ndim*Ddim];          // 16 MB q (fp16)
__device__ __half g_kh[Sdim*Bdim*Ndim*Ddim];          // 16 MB k (fp16)
__device__ __half g_vh[Sdim*Bdim*Ndim*Ddim];          // 16 MB v (fp16)
__device__ __half g_dh[(size_t)Sdim*Bdim*Hdim*NNdim]; // 256 MB dots (fp16)
__device__ __half g_ph[(size_t)Sdim*Bdim*Hdim*NNdim]; // 256 MB probs (fp16)
__device__ __half g_combh[Bdim*Ndim*Ddim];            // 4 MB combined (fp16)
__device__ float  g_xmean[Bdim*Ddim];
__device__ float  g_params[16];                       // [0]=1/temp, [1..4]=gw, [5..12]=coh[b][s]

// ---------------- helpers ----------------
__device__ __forceinline__ void mma_f16(float* d, const unsigned* a, const unsigned* b) {
    asm volatile(
        "mma.sync.aligned.m16n8k16.row.col.f32.f16.f16.f32 "
        "{%0,%1,%2,%3},{%4,%5,%6,%7},{%8,%9},{%0,%1,%2,%3};"
        : "+f"(d[0]), "+f"(d[1]), "+f"(d[2]), "+f"(d[3])
        : "r"(a[0]), "r"(a[1]), "r"(a[2]), "r"(a[3]), "r"(b[0]), "r"(b[1]));
}

__device__ __forceinline__ void cpa16(unsigned saddr, const void* gptr) {
    asm volatile("cp.async.cg.shared.global [%0], [%1], 16;\n" :: "r"(saddr), "l"(gptr));
}
__device__ __forceinline__ void cpa_commit() {
    asm volatile("cp.async.commit_group;\n");
}

// ---------------- fp32 -> fp16 bulk convert ----------------
__global__ void f2h_kernel(const float* __restrict__ src, __half* __restrict__ dst,
                           long long n) {
    long long i = ((long long)blockIdx.x * blockDim.x + threadIdx.x) * 8;
    if (i >= n) return;
    float4 a = *(const float4*)(src + i);
    float4 b = *(const float4*)(src + i + 4);
    __half2 h0 = __floats2half2_rn(a.x, a.y);
    __half2 h1 = __floats2half2_rn(a.z, a.w);
    __half2 h2 = __floats2half2_rn(b.x, b.y);
    __half2 h3 = __floats2half2_rn(b.z, b.w);
    uint4 u;
    u.x = *(unsigned*)&h0; u.y = *(unsigned*)&h1;
    u.z = *(unsigned*)&h2; u.w = *(unsigned*)&h3;
    *(uint4*)(dst + i) = u;
}

// ---------------- mean pool over tokens ----------------
__global__ void xmean_kernel(const float* __restrict__ x) {
    int idx = blockIdx.x * blockDim.x + threadIdx.x;  // b*D + d
    if (idx >= Bdim * Ddim) return;
    int b = idx / Ddim, d = idx % Ddim;
    const float* p = x + (long long)b * Ndim * Ddim + d;
    float acc = 0.f;
    for (int n = 0; n < Ndim; n++) acc += p[(long long)n * Ddim];
    g_xmean[idx] = acc * (1.0f / Ndim);
}

// ---------------- temp clip, gate weights, coherence gate ----------------
__global__ void prep_kernel(const float* __restrict__ Wg, const float* __restrict__ bg,
                            const float* __restrict__ hyp_w,
                            const float* __restrict__ temperature) {
    int t = threadIdx.x;
    int warp = t / 32, lane = t % 32;
    if (warp < Bdim * Sdim) {
        int b = warp / Sdim, s = warp % Sdim;
        float acc = 0.f;
        for (int d = lane; d < Ddim; d += 32)
            acc += g_xmean[b * Ddim + d] * Wg[s * Ddim + d];
        #pragma unroll
        for (int o = 16; o > 0; o >>= 1) acc += __shfl_down_sync(0xffffffff, acc, o);
        if (lane == 0) {
            float vv = acc + bg[s];
            g_params[5 + b * Sdim + s] = 1.0f / (1.0f + expf(-vv));
        }
    }
    if (t == 0) {
        float tp = fminf(fmaxf(temperature[0], 0.1f), 10.0f);
        g_params[0] = 1.0f / tp;
        float hw[Sdim];
        float m = -1e30f;
        for (int s = 0; s < Sdim; s++) { hw[s] = hyp_w[s] / tp; m = fmaxf(m, hw[s]); }
        float sum = 0.f;
        for (int s = 0; s < Sdim; s++) { hw[s] = expf(hw[s] - m); sum += hw[s]; }
        for (int s = 0; s < Sdim; s++) g_params[1 + s] = hw[s] / sum;
    }
}

// ---------------- all-fp16 tensor-core batched C = alpha * A * B^T (+bias) ----------------
// A: __half [M,K] (lda), B: __half [N,K] (ldb), C row-major (ldc).
// cp.async 3-stage pipeline, KT=64. offsets in elements:
// offX = (z % zmod)*sXlo + (z / zmod)*sXhi
template<bool OUTHALF>
__global__ void __launch_bounds__(512) gemmh(
    const __half* __restrict__ Aall, const __half* __restrict__ Ball,
    void* __restrict__ Call_, const float* __restrict__ bias,
    int K, int lda, int ldb, int ldc,
    int zmod, long long sAlo, long long sAhi,
    long long sBlo, long long sBhi, long long sClo, long long sChi, float alpha)
{
    constexpr int BM = 128, BN = 128, WM = 32, WN = 32;
    constexpr int MT = 2, NT = 4;
    constexpr int KT = 64;
    constexpr int LDW = 36;                   // words per smem row (64 halves + pad)
    constexpr int SLOT = 2 * BM * LDW;        // words per stage (A+B)

    extern __shared__ unsigned smw[];         // 3 stages

    int z = blockIdx.z;
    const __half* A = Aall + (long long)(z % zmod) * sAlo + (long long)(z / zmod) * sAhi;
    const __half* B = Ball + (long long)(z % zmod) * sBlo + (long long)(z / zmod) * sBhi;
    long long offC = (long long)(z % zmod) * sClo + (long long)(z / zmod) * sChi;

    int m0 = blockIdx.y * BM;
    int n0 = blockIdx.x * BN;
    int t = threadIdx.x;
    int lane = t & 31, w = t >> 5;
    int wr = w >> 2, wc = w & 3;
    int g = lane >> 2, c4 = lane & 3;

    unsigned sbase = (unsigned)__cvta_generic_to_shared(smw);

    float acc[MT][NT][4];
    #pragma unroll
    for (int mt = 0; mt < MT; mt++)
        #pragma unroll
        for (int nt = 0; nt < NT; nt++)
            #pragma unroll
            for (int i = 0; i < 4; i++) acc[mt][nt][i] = 0.f;

    const int numT = K / KT;

    auto loadT = [&](int kt, int sl) {
        unsigned sb = sbase + (unsigned)(sl * SLOT) * 4u;
        #pragma unroll
        for (int i = 0; i < 2; i++) {
            int ch = t + i * 512;
            int row = ch >> 3, cw = (ch & 7) * 4;
            cpa16(sb + (unsigned)(row * LDW + cw) * 4u,
                  A + (long long)(m0 + row) * lda + kt * KT + cw * 2);
        }
        #pragma unroll
        for (int i = 0; i < 2; i++) {
            int ch = t + i * 512;
            int row = ch >> 3, cw = (ch & 7) * 4;
            cpa16(sb + (unsigned)(BM * LDW + row * LDW + cw) * 4u,
                  B + (long long)(n0 + row) * ldb + kt * KT + cw * 2);
        }
        cpa_commit();
    };

    loadT(0, 0);
    if (numT > 1) loadT(1, 1);

    for (int kt = 0; kt < numT; kt++) {
        if (kt + 1 < numT) asm volatile("cp.async.wait_group 1;\n");
        else               asm volatile("cp.async.wait_group 0;\n");
        __syncthreads();

        const unsigned* Ab = smw + (kt % 3) * SLOT;
        const unsigned* Bb = Ab + BM * LDW;
        #pragma unroll
        for (int ks = 0; ks < 4; ks++) {
            int kb = ks * 8 + c4;
            unsigned afr[MT][4], bfr[NT][2];
            #pragma unroll
            for (int mt = 0; mt < MT; mt++) {
                const unsigned* pA = Ab + (wr * WM + mt * 16 + g) * LDW;
                afr[mt][0] = pA[kb];
                afr[mt][1] = pA[8 * LDW + kb];
                afr[mt][2] = pA[kb + 4];
                afr[mt][3] = pA[8 * LDW + kb + 4];
            }
            #pragma unroll
            for (int nt = 0; nt < NT; nt++) {
                const unsigned* pB = Bb + (wc * WN + nt * 8 + g) * LDW;
                bfr[nt][0] = pB[kb];
                bfr[nt][1] = pB[kb + 4];
            }
            #pragma unroll
            for (int mt = 0; mt < MT; mt++)
                #pragma unroll
                for (int nt = 0; nt < NT; nt++)
                    mma_f16(acc[mt][nt], afr[mt], bfr[nt]);
        }
        if (kt + 2 < numT) loadT(kt + 2, (kt + 2) % 3);
    }

    // epilogue
    #pragma unroll
    for (int mt = 0; mt < MT; mt++) {
        int r = m0 + wr * WM + mt * 16 + g;
        #pragma unroll
        for (int nt = 0; nt < NT; nt++) {
            int c = n0 + wc * WN + nt * 8 + c4 * 2;
            if constexpr (OUTHALF) {
                __half* C = (__half*)Call_ + offC;
                __half2 v0 = __floats2half2_rn(acc[mt][nt][0] * alpha, acc[mt][nt][1] * alpha);
                __half2 v1 = __floats2half2_rn(acc[mt][nt][2] * alpha, acc[mt][nt][3] * alpha);
                *(__half2*)(C + (long long)r * ldc + c) = v0;
                *(__half2*)(C + (long long)(r + 8) * ldc + c) = v1;
            } else {
                float* C = (float*)Call_ + offC;
                float b0 = 0.f, b1 = 0.f;
                if (bias) { b0 = bias[c]; b1 = bias[c + 1]; }
                *(float2*)(C + (long long)r * ldc + c) =
                    make_float2(acc[mt][nt][0] * alpha + b0, acc[mt][nt][1] * alpha + b1);
                *(float2*)(C + (long long)(r + 8) * ldc + c) =
                    make_float2(acc[mt][nt][2] * alpha + b0, acc[mt][nt][3] * alpha + b1);
            }
        }
    }
}

// ---------------- fused softmax + combined_attn reduce ----------------
// block = (i, b). 8 warps x 8 rows each = 64 (s,h) dots rows for token i.
// Each warp: full-row softmax with shuffle-only reductions, writes fp16 probs,
// accumulates gw[s]*p in registers. Cross-warp smem reduce -> out2[b,i,:].
__global__ void __launch_bounds__(256) softmax_reduce_kernel(float* __restrict__ outAttn) {
    __shared__ float Sacc[8 * 1032];
    int i = blockIdx.x;
    int b = blockIdx.y;
    int t = threadIdx.x;
    int lane = t & 31, w = t >> 5;
    float invT = g_params[0];

    float acc[32];
    #pragma unroll
    for (int u = 0; u < 32; u++) acc[u] = 0.f;

    #pragma unroll 1
    for (int j = 0; j < 8; j++) {
        int r = w * 8 + j;                 // 0..63
        int s = r >> 4, h = r & 15;
        size_t z = (size_t)((s * Bdim + b) * Hdim + h);
        const __half* drow = g_dh + z * NNdim + (size_t)i * Ndim;

        uint4 u4[4];
        #pragma unroll
        for (int c = 0; c < 4; c++)
            u4[c] = *(const uint4*)(drow + c * 256 + lane * 8);

        float v[32];
        #pragma unroll
        for (int c = 0; c < 4; c++) {
            __half2* hp = (__half2*)&u4[c];
            #pragma unroll
            for (int q = 0; q < 4; q++) {
                float2 f = __half22float2(hp[q]);
                v[c * 8 + q * 2]     = f.x * invT;
                v[c * 8 + q * 2 + 1] = f.y * invT;
            }
        }
        float mx = -1e30f;
        #pragma unroll
        for (int u = 0; u < 32; u++) mx = fmaxf(mx, v[u]);
        #pragma unroll
        for (int o = 16; o > 0; o >>= 1) mx = fmaxf(mx, __shfl_xor_sync(0xffffffffu, mx, o));
        float sm = 0.f;
        #pragma unroll
        for (int u = 0; u < 32; u++) { v[u] = __expf(v[u] - mx); sm += v[u]; }
        #pragma unroll
        for (int o = 16; o > 0; o >>= 1) sm += __shfl_xor_sync(0xffffffffu, sm, o);
        float inv = 1.0f / sm;
        float gwv = g_params[1 + s];

        __half* prow = g_ph + z * NNdim + (size_t)i * Ndim;
        #pragma unroll
        for (int c = 0; c < 4; c++) {
            __half2 hh[4];
            #pragma unroll
            for (int q = 0; q < 4; q++) {
                float p0 = v[c * 8 + q * 2] * inv;
                float p1 = v[c * 8 + q * 2 + 1] * inv;
                hh[q] = __floats2half2_rn(p0, p1);
                acc[c * 8 + q * 2]     += gwv * p0;
                acc[c * 8 + q * 2 + 1] += gwv * p1;
            }
            uint4 o4;
            o4.x = *(unsigned*)&hh[0]; o4.y = *(unsigned*)&hh[1];
            o4.z = *(unsigned*)&hh[2]; o4.w = *(unsigned*)&hh[3];
            *(uint4*)(prow + c * 256 + lane * 8) = o4;
        }
    }

    // cross-warp reduce into out2 row
    #pragma unroll
    for (int c = 0; c < 4; c++) {
        float4 a0 = make_float4(acc[c*8+0], acc[c*8+1], acc[c*8+2], acc[c*8+3]);
        float4 a1 = make_float4(acc[c*8+4], acc[c*8+5], acc[c*8+6], acc[c*8+7]);
        *(float4*)(Sacc + w * 1032 + c * 256 + lane * 8)     = a0;
        *(float4*)(Sacc + w * 1032 + c * 256 + lane * 8 + 4) = a1;
    }
    __syncthreads();

    float4 o;
    float* op = &o.x;
    #pragma unroll
    for (int q = 0; q < 4; q++) {
        int col = t * 4 + q;
        float sum = 0.f;
        #pragma unroll
        for (int wv = 0; wv < 8; wv++) sum += Sacc[wv * 1032 + col];
        op[q] = sum * (1.0f / Hdim);
    }
    *(float4*)(outAttn + ((size_t)b * Ndim + i) * Ndim + t * 4) = o;
}

// ---------------- fused P@V + gate + combine (all fp16 mma) ----------------
__global__ void __launch_bounds__(256) pv_combine_kernel() {
    constexpr int KT2 = 32;
    constexpr int BM = 128, BN = 64, WM = 32, WN = 32;
    constexpr int MT = 2, NT = 4;
    constexpr int LDA = 20;
    constexpr int LDB = 72;
    constexpr int ASZ = BM * LDA;
    constexpr int BSZ = (KT2 / 2) * LDB;

    __shared__ unsigned smw[2 * ASZ + 2 * BSZ];
    unsigned* Aw = smw;
    unsigned* Bw = smw + 2 * ASZ;

    int zz = blockIdx.y;
    int b = zz / Hdim, h = zz % Hdim;
    int m0 = blockIdx.x * BM;

    int t = threadIdx.x;
    int lane = t & 31, w = t >> 5;
    int wr = w >> 1, wc = w & 1;
    int g = lane >> 2, c4 = lane & 3;
    int kp = t >> 4, ng = t & 15;

    float acc[MT][NT][4];
    #pragma unroll
    for (int mt = 0; mt < MT; mt++)
        #pragma unroll
        for (int nt = 0; nt < NT; nt++)
            #pragma unroll
            for (int i = 0; i < 4; i++) acc[mt][nt][i] = 0.f;

    for (int s = 0; s < Sdim; s++) {
        const __half* A = g_ph + (size_t)((s * Bdim + b) * Hdim + h) * NNdim;
        const __half* V = g_vh + (size_t)(s * Bdim + b) * Ndim * Ddim + h * DHdim;
        float ws = g_params[1 + s] * g_params[5 + b * Sdim + s];
        __half2 ws2 = __float2half2_rn(ws);

        uint4 ua[2];
        uint2 va, vb;
        auto loadG = [&](int kt) {
            #pragma unroll
            for (int i = 0; i < 2; i++) {
                int ch = t + i * 256;
                int row = ch >> 2, cw = (ch & 3) * 4;
                ua[i] = *(const uint4*)(A + (size_t)(m0 + row) * Ndim + kt * KT2 + cw * 2);
            }
            int k = kt * KT2 + kp * 2;
            va = *(const uint2*)(V + (size_t)k * Ddim + ng * 4);
            vb = *(const uint2*)(V + (size_t)(k + 1) * Ddim + ng * 4);
        };
        auto storeS = [&](int buf) {
            #pragma unroll
            for (int i = 0; i < 2; i++) {
                int ch = t + i * 256;
                int row = ch >> 2, cw = (ch & 3) * 4;
                *(uint4*)(Aw + buf * ASZ + row * LDA + cw) = ua[i];
            }
            __half2 a01 = *(__half2*)&va.x, a23 = *(__half2*)&va.y;
            __half2 b01 = *(__half2*)&vb.x, b23 = *(__half2*)&vb.y;
            __half2 w0 = __hmul2(__halves2half2(__low2half(a01), __low2half(b01)), ws2);
            __half2 w1 = __hmul2(__halves2half2(__high2half(a01), __high2half(b01)), ws2);
            __half2 w2 = __hmul2(__halves2half2(__low2half(a23), __low2half(b23)), ws2);
            __half2 w3 = __hmul2(__halves2half2(__high2half(a23), __high2half(b23)), ws2);
            uint4 u;
            u.x = *(unsigned*)&w0; u.y = *(unsigned*)&w1;
            u.z = *(unsigned*)&w2; u.w = *(unsigned*)&w3;
            *(uint4*)(Bw + buf * BSZ + kp * LDB + ng * 4) = u;
        };

        const int numT = Ndim / KT2;
        loadG(0);
        if (s > 0) __syncthreads();
        storeS(0);
        for (int kt = 0; kt < numT; kt++) {
            __syncthreads();
            int buf = kt & 1;
            if (kt + 1 < numT) loadG(kt + 1);

            const unsigned* Ab = Aw + buf * ASZ;
            const unsigned* Bb = Bw + buf * BSZ;
            #pragma unroll
            for (int ks = 0; ks < 2; ks++) {
                unsigned afr[MT][4], bfr[NT][2];
                #pragma unroll
                for (int mt = 0; mt < MT; mt++) {
                    const unsigned* pA = Ab + (wr * WM + mt * 16 + g) * LDA + ks * 8;
                    afr[mt][0] = pA[c4];
                    afr[mt][1] = pA[8 * LDA + c4];
                    afr[mt][2] = pA[c4 + 4];
                    afr[mt][3] = pA[8 * LDA + c4 + 4];
                }
                #pragma unroll
                for (int nt = 0; nt < NT; nt++) {
                    int n = wc * WN + nt * 8 + g;
                    bfr[nt][0] = Bb[(ks * 8 + c4) * LDB + n];
                    bfr[nt][1] = Bb[(ks * 8 + 4 + c4) * LDB + n];
                }
                #pragma unroll
                for (int mt = 0; mt < MT; mt++)
                    #pragma unroll
                    for (int nt = 0; nt < NT; nt++)
                        mma_f16(acc[mt][nt], afr[mt], bfr[nt]);
            }
            if (kt + 1 < numT) storeS(1 - buf);
        }
    }

    __half* C = g_combh + (size_t)b * Ndim * Ddim + h * DHdim;
    #pragma unroll
    for (int mt = 0; mt < MT; mt++) {
        int r = m0 + wr * WM + mt * 16 + g;
        #pragma unroll
        for (int nt = 0; nt < NT; nt++) {
            int c = wc * WN + nt * 8 + c4 * 2;
            *(__half2*)(C + (size_t)r * Ddim + c) =
                __floats2half2_rn(acc[mt][nt][0], acc[mt][nt][1]);
            *(__half2*)(C + (size_t)(r + 8) * Ddim + c) =
                __floats2half2_rn(acc[mt][nt][2], acc[mt][nt][3]);
        }
    }
}

// ---------------- launch ----------------
extern "C" void kernel_launch(void* const* d_in, const int* in_sizes, int n_in,
                              void* d_out, int out_size) {
    const float* x    = (const float*)d_in[0];
    const float* Wq   = (const float*)d_in[1];
    const float* Wk   = (const float*)d_in[2];
    const float* Wv   = (const float*)d_in[3];
    const float* Wg   = (const float*)d_in[4];
    const float* bg   = (const float*)d_in[5];
    const float* Wo   = (const float*)d_in[6];
    const float* bo   = (const float*)d_in[7];
    const float* hw   = (const float*)d_in[8];
    const float* temp = (const float*)d_in[9];
    float* out = (float*)d_out;

    void *xh, *wqh, *wkh, *wvh, *woh, *qh, *kh, *vh, *dh, *combh;
    cudaGetSymbolAddress(&xh, g_xh);
    cudaGetSymbolAddress(&wqh, g_wqh);
    cudaGetSymbolAddress(&wkh, g_wkh);
    cudaGetSymbolAddress(&wvh, g_wvh);
    cudaGetSymbolAddress(&woh, g_woh);
    cudaGetSymbolAddress(&qh, g_qh);
    cudaGetSymbolAddress(&kh, g_kh);
    cudaGetSymbolAddress(&vh, g_vh);
    cudaGetSymbolAddress(&dh, g_dh);
    cudaGetSymbolAddress(&combh, g_combh);

    const long long ND = (long long)Ndim * Ddim;
    const long long DD = (long long)Ddim * Ddim;

    const int smem_g = 3 * 2 * 128 * 36 * 4;   // 110592
    cudaFuncSetAttribute(gemmh<true>,
                         cudaFuncAttributeMaxDynamicSharedMemorySize, smem_g);
    cudaFuncSetAttribute(gemmh<false>,
                         cudaFuncAttributeMaxDynamicSharedMemorySize, smem_g);

    // 0) fp16 conversions
    f2h_kernel<<<(unsigned)(Bdim * ND / 8 / 256), 256>>>(x, (__half*)xh, Bdim * ND);
    f2h_kernel<<<(unsigned)(Sdim * DD / 8 / 256), 256>>>(Wq, (__half*)wqh, Sdim * DD);
    f2h_kernel<<<(unsigned)(Sdim * DD / 8 / 256), 256>>>(Wk, (__half*)wkh, Sdim * DD);
    f2h_kernel<<<(unsigned)(Sdim * DD / 8 / 256), 256>>>(Wv, (__half*)wvh, Sdim * DD);
    f2h_kernel<<<(unsigned)(DD / 8 / 256), 256>>>(Wo, (__half*)woh, DD);

    // 1) mean pool + gates
    xmean_kernel<<<(Bdim * Ddim + 255) / 256, 256>>>(x);
    prep_kernel<<<1, 256>>>(Wg, bg, hw, temp);

    // 2) projections: q/k/v all fp16 out   (z = s*B + b)
    dim3 gproj(Ndim / 128, Ndim / 128, Sdim * Bdim);
    gemmh<true><<<gproj, 512, smem_g>>>(
        (const __half*)xh, (const __half*)wqh, qh, nullptr,
        Ddim, Ddim, Ddim, Ddim,
        Bdim, ND, 0LL, 0LL, DD, ND, (long long)Bdim * ND, 1.0f);
    gemmh<true><<<gproj, 512, smem_g>>>(
        (const __half*)xh, (const __half*)wkh, kh, nullptr,
        Ddim, Ddim, Ddim, Ddim,
        Bdim, ND, 0LL, 0LL, DD, ND, (long long)Bdim * ND, 1.0f);
    gemmh<true><<<gproj, 512, smem_g>>>(
        (const __half*)xh, (const __half*)wvh, vh, nullptr,
        Ddim, Ddim, Ddim, Ddim,
        Bdim, ND, 0LL, 0LL, DD, ND, (long long)Bdim * ND, 1.0f);

    // 3) dots[s,b,h] = 0.125 * Q K^T -> fp16   (z = sb*H + h, zmod=H)
    dim3 gdots(Ndim / 128, Ndim / 128, Sdim * Bdim * Hdim);
    gemmh<true><<<gdots, 512, smem_g>>>(
        (const __half*)qh, (const __half*)kh, dh, nullptr,
        DHdim, Ddim, Ddim, Ndim,
        Hdim, (long long)DHdim, ND, (long long)DHdim, ND,
        (long long)NNdim, (long long)Hdim * NNdim, 0.125f);

    // 4) fused softmax + combined_attn reduce -> probs + second output
    dim3 gsm(Ndim, Bdim);
    softmax_reduce_kernel<<<gsm, 256>>>(out + (long long)Bdim * ND);

    // 5) fused P@V + gate + combine -> g_combh (fp16, fp16 mma)
    dim3 gpv(Ndim / 128, Bdim * Hdim);
    pv_combine_kernel<<<gpv, 256>>>();

    // 6) y = combined @ Wo^T + bo -> first output (fp32 + bias)
    dim3 gfin(Ndim / 128, Ndim / 128, Bdim);
    gemmh<false><<<gfin, 512, smem_g>>>(
        (const __half*)combh, (const __half*)woh, out, bo,
        Ddim, Ddim, Ddim, Ddim,
        1, 0LL, ND, 0LL, 0LL, 0LL, ND, 1.0f);
}